// round 1
// baseline (speedup 1.0000x reference)
#include <cuda_runtime.h>
#include <cstdint>

// ---------------------------------------------------------------------------
// MultiPathLayer: N=50000 nodes, E=800000 edges, D=128.
// Restructured: all edge-space matmuls moved to node space.
// ---------------------------------------------------------------------------

#define NMAX 50000
#define DDIM 128

// Scratch buffers (static device memory — allowed; no runtime allocation).
__device__ float4 g_b0 [NMAX * 32];   // Un   -> later E0
__device__ float4 g_b1 [NMAX * 32];   // Vn   -> later E1
__device__ float4 g_b2 [NMAX * 32];   // Ue   -> later E2
__device__ float4 g_b3 [NMAX * 32];   // Ve   -> later Att
__device__ float4 g_b4 [NMAX * 32];   // Hini -> later Hagg
__device__ float4 g_b5 [NMAX * 32];   // Einit
__device__ float4 g_b6 [NMAX * 32];   // Pn   -> later HR
__device__ float4 g_b7 [NMAX * 32];   // Pe
__device__ float4 g_b8 [NMAX * 32];   // T
__device__ float4 g_b9 [NMAX * 32];   // Fn
__device__ float4 g_b10[NMAX * 32];   // Fe
__device__ float4 g_b11[NMAX * 32];   // Qp
__device__ float4 g_b12[NMAX * 32];   // Q
__device__ float4 g_b13[NMAX * 32];   // Fs
__device__ float  g_s[NMAX];
__device__ float  g_deg[NMAX];
__device__ float  g_bnsum[DDIM];
__device__ float  g_bnsq[DDIM];

// mish(x) = x * tanh(softplus(x)) = x * (t^2-1)/(t^2+1), t = 1+e^x
__device__ __forceinline__ float mishf(float x) {
    float e  = __expf(fminf(x, 30.0f));
    float t  = 1.0f + e;
    float t2 = t * t;
    return x * __fdividef(t2 - 1.0f, t2 + 1.0f);
}

// Vectorized global reduction (sm_90+): 4 float adds in one red instruction.
__device__ __forceinline__ void red_add_v4(float4* p, float4 v) {
    asm volatile("red.global.add.v4.f32 [%0], {%1,%2,%3,%4};"
                 :: "l"(p), "f"(v.x), "f"(v.y), "f"(v.z), "f"(v.w)
                 : "memory");
}

// ---------------------------------------------------------------------------
// Generic fused GEMM: C[n,128] = act( rowScale ⊙ (A@W) + (A2@W2) +
//                                     biasRowScale ⊙ bias + Cadd )
// K = 128 fixed. Block: 64 rows x 128 cols, 256 threads, each thread 4x8.
// actMode: 0 = linear, 1 = mish, 2 = mish(mish)
// ---------------------------------------------------------------------------
__global__ void __launch_bounds__(256) gemm128_kernel(
    const float* __restrict__ A,  const float* __restrict__ W,
    const float* __restrict__ A2, const float* __restrict__ W2,
    const float* __restrict__ rowScale,
    const float* __restrict__ bias,
    const float* __restrict__ biasRowScale,
    const float* __restrict__ Cadd,
    float* __restrict__ C, int n, int actMode)
{
    __shared__ float As[64][36];
    __shared__ float Ws[32][128];

    const int t  = threadIdx.x;
    const int tx = t & 15;    // col group: cols [tx*8, tx*8+8)
    const int ty = t >> 4;    // row group: rows [ty*4, ty*4+4)
    const int rowBase = blockIdx.x * 64;

    float acc[4][8];
    #pragma unroll
    for (int i = 0; i < 4; i++)
        #pragma unroll
        for (int j = 0; j < 8; j++) acc[i][j] = 0.0f;

    const int nPass = A2 ? 2 : 1;
    for (int pass = 0; pass < nPass; ++pass) {
        const float* Ap = pass ? A2 : A;
        const float* Wp = pass ? W2 : W;

        for (int kb = 0; kb < 4; ++kb) {
            __syncthreads();
            // A tile: 64 x 32
            {
                int r0 = t >> 3;           // 0..31
                int c4 = t & 7;            // 0..7 (float4 column)
                #pragma unroll
                for (int half = 0; half < 2; ++half) {
                    int r = r0 + half * 32;
                    int grow = rowBase + r;
                    float4 v = make_float4(0.f, 0.f, 0.f, 0.f);
                    if (grow < n)
                        v = *(const float4*)&Ap[grow * 128 + kb * 32 + c4 * 4];
                    *(float4*)&As[r][c4 * 4] = v;
                }
            }
            // W tile: 32 x 128 (rows kb*32 .. kb*32+31)
            {
                const float4* Wp4 = (const float4*)&Wp[kb * 32 * 128];
                float4* Ws4 = (float4*)Ws;
                #pragma unroll
                for (int it = 0; it < 4; ++it)
                    Ws4[t + 256 * it] = Wp4[t + 256 * it];
            }
            __syncthreads();

            #pragma unroll 8
            for (int k = 0; k < 32; ++k) {
                float4 w0 = *(const float4*)&Ws[k][tx * 8];
                float4 w1 = *(const float4*)&Ws[k][tx * 8 + 4];
                float a[4];
                #pragma unroll
                for (int i = 0; i < 4; i++) a[i] = As[ty * 4 + i][k];
                #pragma unroll
                for (int i = 0; i < 4; i++) {
                    acc[i][0] += a[i] * w0.x; acc[i][1] += a[i] * w0.y;
                    acc[i][2] += a[i] * w0.z; acc[i][3] += a[i] * w0.w;
                    acc[i][4] += a[i] * w1.x; acc[i][5] += a[i] * w1.y;
                    acc[i][6] += a[i] * w1.z; acc[i][7] += a[i] * w1.w;
                }
            }
        }
        if (pass == 0 && rowScale) {
            #pragma unroll
            for (int i = 0; i < 4; i++) {
                int grow = rowBase + ty * 4 + i;
                float rs = (grow < n) ? rowScale[grow] : 0.0f;
                #pragma unroll
                for (int j = 0; j < 8; j++) acc[i][j] *= rs;
            }
        }
    }

    // epilogue
    #pragma unroll
    for (int i = 0; i < 4; i++) {
        int grow = rowBase + ty * 4 + i;
        if (grow >= n) continue;
        float bscale = biasRowScale ? biasRowScale[grow] : 1.0f;
        float tmp[8];
        #pragma unroll
        for (int j = 0; j < 8; j++) {
            int col = tx * 8 + j;
            float v = acc[i][j];
            if (bias) v += bias[col] * bscale;
            if (Cadd) v += Cadd[grow * 128 + col];
            if (actMode == 1)      v = mishf(v);
            else if (actMode == 2) v = mishf(mishf(v));
            tmp[j] = v;
        }
        *(float4*)&C[grow * 128 + tx * 8]     = make_float4(tmp[0], tmp[1], tmp[2], tmp[3]);
        *(float4*)&C[grow * 128 + tx * 8 + 4] = make_float4(tmp[4], tmp[5], tmp[6], tmp[7]);
    }
}

// ---------------------------------------------------------------------------
// Edge kernel: one warp per edge. Fuses node-path message, edge-path message,
// and struct-path scatter (d2 * x[src]), all via vectorized global reds.
// ---------------------------------------------------------------------------
__global__ void __launch_bounds__(256) edge_kernel(
    const int*   __restrict__ ei,      // [2E]: src = ei[e], dst = ei[E+e]
    const int*   __restrict__ bt,
    const float* __restrict__ coords,
    const float* __restrict__ conv_w,
    const float* __restrict__ conv_b,
    const float* __restrict__ b_el,
    const float* __restrict__ x,
    const float4* __restrict__ Un, const float4* __restrict__ Vn,
    const float4* __restrict__ Ue, const float4* __restrict__ Ve,
    float4* Pn, float4* Pe, float4* T,
    float* s_arr, float* deg_arr, int E)
{
    int e = blockIdx.x * 8 + (threadIdx.x >> 5);
    if (e >= E) return;
    int lane = threadIdx.x & 31;

    int src = ei[e];
    int dst = ei[E + e];
    float norm = conv_w[bt[e]] + conv_b[0];

    float dx = coords[src * 3 + 0] - coords[dst * 3 + 0];
    float dy = coords[src * 3 + 1] - coords[dst * 3 + 1];
    float dz = coords[src * 3 + 2] - coords[dst * 3 + 2];
    float d2 = dx * dx + dy * dy + dz * dz;

    int di = dst * 32 + lane;
    int si = src * 32 + lane;

    // node path: mish(Un[dst] + Vn[src])  (b_nb folded into Un)
    {
        float4 u = Un[di], v = Vn[si], m;
        m.x = mishf(u.x + v.x); m.y = mishf(u.y + v.y);
        m.z = mishf(u.z + v.z); m.w = mishf(u.w + v.w);
        red_add_v4(&Pn[di], m);
    }
    // edge path: mish(norm*(Ue[dst]+Ve[src]) + b_el)
    {
        float4 u = Ue[di], v = Ve[si];
        float4 b = ((const float4*)b_el)[lane];
        float4 m;
        m.x = mishf(norm * (u.x + v.x) + b.x);
        m.y = mishf(norm * (u.y + v.y) + b.y);
        m.z = mishf(norm * (u.z + v.z) + b.z);
        m.w = mishf(norm * (u.w + v.w) + b.w);
        red_add_v4(&Pe[di], m);
    }
    // struct path scatter: T[dst] += d2 * x[src]
    {
        float4 xs = ((const float4*)x)[si];
        float4 m = make_float4(d2 * xs.x, d2 * xs.y, d2 * xs.z, d2 * xs.w);
        red_add_v4(&T[di], m);
    }
    if (lane == 0) {
        atomicAdd(&s_arr[dst], d2);
        atomicAdd(&deg_arr[dst], 1.0f);
    }
}

// ---------------------------------------------------------------------------
// Attention over the 3 paths (softmax along path axis) + weighted sum.
// ---------------------------------------------------------------------------
__global__ void attention_kernel(
    const float4* __restrict__ e0, const float4* __restrict__ e1,
    const float4* __restrict__ e2,
    const float4* __restrict__ f0, const float4* __restrict__ f1,
    const float4* __restrict__ f2,
    float4* __restrict__ att, int n4)
{
    int i = blockIdx.x * blockDim.x + threadIdx.x;
    if (i >= n4) return;
    float4 a0 = e0[i], a1 = e1[i], a2 = e2[i];
    float4 g0 = f0[i], g1 = f1[i], g2 = f2[i];
    float4 o;
    {
        float m = fmaxf(a0.x, fmaxf(a1.x, a2.x));
        float p0 = __expf(a0.x - m), p1 = __expf(a1.x - m), p2 = __expf(a2.x - m);
        o.x = __fdividef(p0 * g0.x + p1 * g1.x + p2 * g2.x, p0 + p1 + p2);
    }
    {
        float m = fmaxf(a0.y, fmaxf(a1.y, a2.y));
        float p0 = __expf(a0.y - m), p1 = __expf(a1.y - m), p2 = __expf(a2.y - m);
        o.y = __fdividef(p0 * g0.y + p1 * g1.y + p2 * g2.y, p0 + p1 + p2);
    }
    {
        float m = fmaxf(a0.z, fmaxf(a1.z, a2.z));
        float p0 = __expf(a0.z - m), p1 = __expf(a1.z - m), p2 = __expf(a2.z - m);
        o.z = __fdividef(p0 * g0.z + p1 * g1.z + p2 * g2.z, p0 + p1 + p2);
    }
    {
        float m = fmaxf(a0.w, fmaxf(a1.w, a2.w));
        float p0 = __expf(a0.w - m), p1 = __expf(a1.w - m), p2 = __expf(a2.w - m);
        o.w = __fdividef(p0 * g0.w + p1 * g1.w + p2 * g2.w, p0 + p1 + p2);
    }
    att[i] = o;
}

// ---------------------------------------------------------------------------
// BatchNorm statistics: per-column sum and sum-of-squares.
// ---------------------------------------------------------------------------
__global__ void bnstat_kernel(const float* __restrict__ H,
                              float* sum, float* sq, int n)
{
    int d  = threadIdx.x;           // 128 threads
    int r0 = blockIdx.x * 256;
    int r1 = min(r0 + 256, n);
    float s = 0.f, q = 0.f;
    for (int r = r0; r < r1; ++r) {
        float v = H[r * 128 + d];
        s += v; q += v * v;
    }
    atomicAdd(&sum[d], s);
    atomicAdd(&sq[d],  q);
}

__global__ void final_kernel(const float* __restrict__ H,
                             const float* __restrict__ sum,
                             const float* __restrict__ sq,
                             const float* __restrict__ gamma,
                             const float* __restrict__ beta,
                             float* __restrict__ out, int n)
{
    int i = blockIdx.x * blockDim.x + threadIdx.x;
    if (i >= n * 128) return;
    int d = i & 127;
    float invn = 1.0f / (float)n;
    float mean = sum[d] * invn;
    float var  = sq[d] * invn - mean * mean;
    float v = (H[i] - mean) * rsqrtf(var + 1e-5f) * gamma[d] + beta[d];
    out[i] = mishf(v);
}

// ---------------------------------------------------------------------------
// Host launch
// ---------------------------------------------------------------------------
static float* symaddr(const void* sym) {
    void* p = nullptr;
    cudaGetSymbolAddress(&p, sym);
    return (float*)p;
}

extern "C" void kernel_launch(void* const* d_in, const int* in_sizes, int n_in,
                              void* d_out, int out_size)
{
    const float* x       = (const float*)d_in[0];
    const float* coords  = (const float*)d_in[1];
    const int*   ei      = (const int*)  d_in[2];
    const int*   bt      = (const int*)  d_in[3];
    const float* W_nb    = (const float*)d_in[4];
    const float* b_nb    = (const float*)d_in[5];
    const float* W_nout  = (const float*)d_in[6];
    const float* b_nout  = (const float*)d_in[7];
    const float* conv_w  = (const float*)d_in[8];
    const float* conv_b  = (const float*)d_in[9];
    const float* W_el    = (const float*)d_in[10];
    const float* b_el    = (const float*)d_in[11];
    const float* W_eout  = (const float*)d_in[12];
    const float* b_eout  = (const float*)d_in[13];
    const float* W_coord = (const float*)d_in[14];
    const float* b_coord = (const float*)d_in[15];
    const float* W_pair  = (const float*)d_in[16];
    const float* b_pair  = (const float*)d_in[17];
    const float* W_sout  = (const float*)d_in[18];
    const float* b_sout  = (const float*)d_in[19];
    const float* W_init  = (const float*)d_in[20];
    const float* feat_lin= (const float*)d_in[21];
    const float* W_att   = (const float*)d_in[22];
    const float* W_agg   = (const float*)d_in[23];
    const float* gamma   = (const float*)d_in[24];
    const float* beta    = (const float*)d_in[25];

    const int N = in_sizes[0] / 128;
    const int E = in_sizes[2] / 2;

    float* Un    = symaddr(g_b0);
    float* Vn    = symaddr(g_b1);
    float* Ue    = symaddr(g_b2);
    float* Ve    = symaddr(g_b3);
    float* Hini  = symaddr(g_b4);
    float* Einit = symaddr(g_b5);
    float* Pn    = symaddr(g_b6);
    float* Pe    = symaddr(g_b7);
    float* T     = symaddr(g_b8);
    float* Fn    = symaddr(g_b9);
    float* Fe    = symaddr(g_b10);
    float* Qp    = symaddr(g_b11);
    float* Q     = symaddr(g_b12);
    float* Fs    = symaddr(g_b13);
    float* sArr  = symaddr(g_s);
    float* dArr  = symaddr(g_deg);
    float* bnS   = symaddr(g_bnsum);
    float* bnQ   = symaddr(g_bnsq);
    // reuse
    float* E0 = Un; float* E1 = Vn; float* E2 = Ue;
    float* Att = Ve; float* Hagg = Hini; float* HR = Pn;

    const size_t vecBytes = (size_t)N * 128 * sizeof(float);
    cudaMemsetAsync(Pn,  0, vecBytes);
    cudaMemsetAsync(Pe,  0, vecBytes);
    cudaMemsetAsync(T,   0, vecBytes);
    cudaMemsetAsync(sArr, 0, N * sizeof(float));
    cudaMemsetAsync(dArr, 0, N * sizeof(float));
    cudaMemsetAsync(bnS, 0, 128 * sizeof(float));
    cudaMemsetAsync(bnQ, 0, 128 * sizeof(float));

    const float* Wnb_top = W_nb;
    const float* Wnb_bot = W_nb + 128 * 128;
    const float* Wel_top = W_el;
    const float* Wel_bot = W_el + 128 * 128;
    const float* Wc_top  = W_coord;
    const float* Wc_bot  = W_coord + 128 * 128;
    const float* Ws_top  = W_sout;
    const float* Ws_bot  = W_sout + 128 * 128;
    const float* Watt_top = W_att;
    const float* Watt_bot = W_att + 128 * 128;

    dim3 gb(256);
    dim3 gg((N + 63) / 64);

    // --- pre-phase projections (node space) ---
    gemm128_kernel<<<gg, gb>>>(x, Wnb_top, nullptr, nullptr, nullptr, b_nb,   nullptr, nullptr, Un,   N, 0);
    gemm128_kernel<<<gg, gb>>>(x, Wnb_bot, nullptr, nullptr, nullptr, nullptr,nullptr, nullptr, Vn,   N, 0);
    gemm128_kernel<<<gg, gb>>>(x, Wel_top, nullptr, nullptr, nullptr, nullptr,nullptr, nullptr, Ue,   N, 0);
    gemm128_kernel<<<gg, gb>>>(x, Wel_bot, nullptr, nullptr, nullptr, nullptr,nullptr, nullptr, Ve,   N, 0);
    gemm128_kernel<<<gg, gb>>>(x, W_init,  nullptr, nullptr, nullptr, nullptr,nullptr, nullptr, Hini, N, 2);
    gemm128_kernel<<<gg, gb>>>(Hini, Watt_top, nullptr, nullptr, nullptr, nullptr, nullptr, nullptr, Einit, N, 0);

    // --- edge scatter phase ---
    edge_kernel<<<(E + 7) / 8, 256>>>(ei, bt, coords, conv_w, conv_b, b_el, x,
                                      (const float4*)Un, (const float4*)Vn,
                                      (const float4*)Ue, (const float4*)Ve,
                                      (float4*)Pn, (float4*)Pe, (float4*)T,
                                      sArr, dArr, E);

    // --- post-phase ---
    gemm128_kernel<<<gg, gb>>>(Pn, W_nout, nullptr, nullptr, nullptr, b_nout, nullptr, nullptr, Fn, N, 1);
    gemm128_kernel<<<gg, gb>>>(Pe, W_eout, nullptr, nullptr, nullptr, b_eout, nullptr, nullptr, Fe, N, 1);
    // Qpre = s ⊙ (x@Wc_top) + T@Wc_bot + deg ⊙ b_coord
    gemm128_kernel<<<gg, gb>>>(x, Wc_top, T, Wc_bot, sArr, b_coord, dArr, nullptr, Qp, N, 0);
    gemm128_kernel<<<gg, gb>>>(Qp, W_pair, nullptr, nullptr, nullptr, b_pair, nullptr, nullptr, Q, N, 1);
    gemm128_kernel<<<gg, gb>>>(x, Ws_top, Q, Ws_bot, nullptr, b_sout, nullptr, nullptr, Fs, N, 1);

    // attention logits per path: e_f = Einit + mish(mish(f @ FL_f)) @ Watt_bot
    gemm128_kernel<<<gg, gb>>>(Fn, feat_lin,               nullptr, nullptr, nullptr, nullptr, nullptr, nullptr, HR, N, 2);
    gemm128_kernel<<<gg, gb>>>(HR, Watt_bot,               nullptr, nullptr, nullptr, nullptr, nullptr, Einit,   E0, N, 0);
    gemm128_kernel<<<gg, gb>>>(Fe, feat_lin + 128 * 128,   nullptr, nullptr, nullptr, nullptr, nullptr, nullptr, HR, N, 2);
    gemm128_kernel<<<gg, gb>>>(HR, Watt_bot,               nullptr, nullptr, nullptr, nullptr, nullptr, Einit,   E1, N, 0);
    gemm128_kernel<<<gg, gb>>>(Fs, feat_lin + 2 * 128 * 128,nullptr, nullptr, nullptr, nullptr, nullptr, nullptr, HR, N, 2);
    gemm128_kernel<<<gg, gb>>>(HR, Watt_bot,               nullptr, nullptr, nullptr, nullptr, nullptr, Einit,   E2, N, 0);

    int n4 = N * 32;
    attention_kernel<<<(n4 + 255) / 256, 256>>>(
        (const float4*)E0, (const float4*)E1, (const float4*)E2,
        (const float4*)Fn, (const float4*)Fe, (const float4*)Fs,
        (float4*)Att, n4);

    gemm128_kernel<<<gg, gb>>>(Att, W_agg, nullptr, nullptr, nullptr, nullptr, nullptr, nullptr, Hagg, N, 0);

    bnstat_kernel<<<(N + 255) / 256, 128>>>(Hagg, bnS, bnQ, N);
    final_kernel<<<(N * 128 + 255) / 256, 256>>>(Hagg, bnS, bnQ, gamma, beta,
                                                 (float*)d_out, N);
}

// round 3
// speedup vs baseline: 1.3789x; 1.3789x over previous
#include <cuda_runtime.h>
#include <cuda_bf16.h>
#include <cstdint>

// ---------------------------------------------------------------------------
// MultiPathLayer: N=50000 nodes, E=800000 edges, D=128.
// GEMMs via mma.sync bf16 (split-bf16, fp32 accuracy). tcgen05 unavailable
// (harness PTX target is compute_103, not 103a).
// ---------------------------------------------------------------------------

#define NMAX 50000
#define DDIM 128
#define WPAD 136           // padded row length in bf16 (68 words) — conflict-free
#define WELEMS (128 * WPAD)

__device__ float4 g_b0 [NMAX * 32];   // Un   -> later E0
__device__ float4 g_b1 [NMAX * 32];   // Vn   -> later E1
__device__ float4 g_b2 [NMAX * 32];   // Ue   -> later E2
__device__ float4 g_b3 [NMAX * 32];   // Ve   -> later Att
__device__ float4 g_b4 [NMAX * 32];   // Hini -> later Hagg
__device__ float4 g_b5 [NMAX * 32];   // Einit
__device__ float4 g_b6 [NMAX * 32];   // Pn   -> later HR
__device__ float4 g_b7 [NMAX * 32];   // Pe
__device__ float4 g_b8 [NMAX * 32];   // T
__device__ float4 g_b9 [NMAX * 32];   // Fn
__device__ float4 g_b10[NMAX * 32];   // Fe
__device__ float4 g_b11[NMAX * 32];   // Qp
__device__ float4 g_b12[NMAX * 32];   // Q
__device__ float4 g_b13[NMAX * 32];   // Fs
__device__ float  g_s[NMAX];
__device__ float  g_deg[NMAX];
__device__ float  g_bnsum[DDIM];
__device__ float  g_bnsq[DDIM];

// Pre-converted weights: [weight][hi/lo][n*WPAD + k] (B operand layout [n][k]).
__device__ __align__(16) __nv_bfloat16 g_wt[18][2][WELEMS];

// mish(x) = x * tanh(softplus(x)) = x * (t^2-1)/(t^2+1), t = 1+e^x
__device__ __forceinline__ float mishf(float x) {
    float e  = __expf(fminf(x, 30.0f));
    float t  = 1.0f + e;
    float t2 = t * t;
    return x * __fdividef(t2 - 1.0f, t2 + 1.0f);
}

__device__ __forceinline__ void red_add_v4(float4* p, float4 v) {
    asm volatile("red.global.add.v4.f32 [%0], {%1,%2,%3,%4};"
                 :: "l"(p), "f"(v.x), "f"(v.y), "f"(v.z), "f"(v.w)
                 : "memory");
}

__device__ __forceinline__ void mma_bf16(float* c, const uint32_t* a,
                                         const uint32_t* b) {
    asm volatile(
        "mma.sync.aligned.m16n8k16.row.col.f32.bf16.bf16.f32 "
        "{%0,%1,%2,%3}, {%4,%5,%6,%7}, {%8,%9}, {%0,%1,%2,%3};"
        : "+f"(c[0]), "+f"(c[1]), "+f"(c[2]), "+f"(c[3])
        : "r"(a[0]), "r"(a[1]), "r"(a[2]), "r"(a[3]), "r"(b[0]), "r"(b[1]));
}

// ---------------------------------------------------------------------------
// Weight setup: W[128,128] fp32 (row-major [k][n]) -> transposed padded hi/lo
// bf16 in g_wt[w].  grid = (18, 8), 256 threads.
// ---------------------------------------------------------------------------
struct WPtrs { const float* p[18]; };

__global__ void setup_weights(WPtrs wp)
{
    int w = blockIdx.x;
    const float* W = wp.p[w];
    __nv_bfloat16* hi = g_wt[w][0];
    __nv_bfloat16* lo = g_wt[w][1];
    // 16384 elems split over 8 y-blocks of 2048, 256 threads -> 8 iters
    for (int it = 0; it < 8; ++it) {
        int idx = blockIdx.y * 2048 + it * 256 + threadIdx.x;
        int k = idx >> 7;
        int n = idx & 127;
        float v = W[idx];
        __nv_bfloat16 h = __float2bfloat16(v);
        __nv_bfloat16 l = __float2bfloat16(v - __bfloat162float(h));
        hi[n * WPAD + k] = h;
        lo[n * WPAD + k] = l;
    }
}

// ---------------------------------------------------------------------------
// mma.sync GEMM: C[n,128] = act( rowScale⊙(A@W[w1]) + (A2@W[w2])
//                                + biasRowScale⊙bias + Cadd )
// K=128.  CTA: 128 rows x 128 cols, 256 threads (8 warps, 4x2).
// Split-bf16: K loop of 24 m16n8k16 steps (hi·hi, lo·hi, hi·lo).
// ---------------------------------------------------------------------------
__global__ void __launch_bounds__(256, 1) mma_gemm(
    const float* __restrict__ A,  int w1,
    const float* __restrict__ A2, int w2,
    const float* __restrict__ rowScale,
    const float* __restrict__ bias,
    const float* __restrict__ biasRowScale,
    const float* __restrict__ Cadd,
    float* __restrict__ C, int n, int actMode)
{
    extern __shared__ __nv_bfloat16 sm[];
    __nv_bfloat16* As_hi = sm;                 // [128][WPAD]
    __nv_bfloat16* As_lo = sm + WELEMS;
    __nv_bfloat16* Bs    = sm + 2 * WELEMS;    // hi then lo, contiguous

    const int tid  = threadIdx.x;
    const int wid  = tid >> 5;
    const int lane = tid & 31;
    const int tq = lane >> 2;       // 0..7
    const int tr = lane & 3;        // 0..3
    const int warpM = wid >> 1;     // 0..3
    const int warpN = wid & 1;      // 0..1
    const int rowBase = blockIdx.x * 128;

    float acc[2][8][4];
    #pragma unroll
    for (int i = 0; i < 2; ++i)
        #pragma unroll
        for (int j = 0; j < 8; ++j)
            #pragma unroll
            for (int q = 0; q < 4; ++q) acc[i][j][q] = 0.0f;

    const int passes = (A2 != nullptr) ? 2 : 1;
    for (int p = 0; p < passes; ++p) {
        const float* Ap  = p ? A2 : A;
        const int    w   = p ? w2 : w1;
        const float* rsp = (p == 0) ? rowScale : nullptr;

        __syncthreads();   // protect smem from previous pass reads

        // ---- A tile: 128x128 fp32 -> hi/lo bf16 (padded) ----
        #pragma unroll 4
        for (int it = 0; it < 16; ++it) {
            int idx = tid + (it << 8);
            int row = idx >> 5;
            int c4  = idx & 31;
            int grow = rowBase + row;
            float4 v = make_float4(0.f, 0.f, 0.f, 0.f);
            if (grow < n) {
                v = *(const float4*)&Ap[grow * 128 + c4 * 4];
                if (rsp) {
                    float s = __ldg(&rsp[grow]);
                    v.x *= s; v.y *= s; v.z *= s; v.w *= s;
                }
            }
            __nv_bfloat16 hx = __float2bfloat16(v.x);
            __nv_bfloat16 hy = __float2bfloat16(v.y);
            __nv_bfloat16 hz = __float2bfloat16(v.z);
            __nv_bfloat16 hw = __float2bfloat16(v.w);
            __nv_bfloat162 h01; h01.x = hx; h01.y = hy;
            __nv_bfloat162 h23; h23.x = hz; h23.y = hw;
            __nv_bfloat162 l01, l23;
            l01.x = __float2bfloat16(v.x - __bfloat162float(hx));
            l01.y = __float2bfloat16(v.y - __bfloat162float(hy));
            l23.x = __float2bfloat16(v.z - __bfloat162float(hz));
            l23.y = __float2bfloat16(v.w - __bfloat162float(hw));
            int o = row * WPAD + c4 * 4;
            *(__nv_bfloat162*)&As_hi[o]     = h01;
            *(__nv_bfloat162*)&As_hi[o + 2] = h23;
            *(__nv_bfloat162*)&As_lo[o]     = l01;
            *(__nv_bfloat162*)&As_lo[o + 2] = l23;
        }
        // ---- B tiles: copy pre-converted hi+lo (2*WELEMS bf16 = 4352 int4) ----
        {
            const int4* src = (const int4*)g_wt[w];
            int4* dst = (int4*)Bs;
            #pragma unroll
            for (int it = 0; it < 17; ++it)
                dst[tid + (it << 8)] = src[tid + (it << 8)];
        }
        __syncthreads();

        // ---- main loop: 24 k-steps (8 hi·hi, 8 lo·hi, 8 hi·lo) ----
        const uint32_t* Ah = (const uint32_t*)As_hi;
        const uint32_t* Al = (const uint32_t*)As_lo;
        const uint32_t* Bh = (const uint32_t*)Bs;
        const uint32_t* Bl = (const uint32_t*)(Bs + WELEMS);

        #pragma unroll 1
        for (int ks = 0; ks < 24; ++ks) {
            int kk  = ks & 7;
            int sel = ks >> 3;
            const uint32_t* Ab = (sel == 1) ? Al : Ah;
            const uint32_t* Bb = (sel == 2) ? Bl : Bh;
            int koff = kk * 8 + tr;

            uint32_t afrag[2][4];
            #pragma unroll
            for (int mt = 0; mt < 2; ++mt) {
                int r = warpM * 32 + mt * 16 + tq;
                afrag[mt][0] = Ab[r * 68 + koff];
                afrag[mt][1] = Ab[(r + 8) * 68 + koff];
                afrag[mt][2] = Ab[r * 68 + koff + 4];
                afrag[mt][3] = Ab[(r + 8) * 68 + koff + 4];
            }
            #pragma unroll
            for (int nt = 0; nt < 8; ++nt) {
                int nrow = warpN * 64 + nt * 8 + tq;
                uint32_t bfrag[2];
                bfrag[0] = Bb[nrow * 68 + koff];
                bfrag[1] = Bb[nrow * 68 + koff + 4];
                mma_bf16(acc[0][nt], afrag[0], bfrag);
                mma_bf16(acc[1][nt], afrag[1], bfrag);
            }
        }
    }

    // ---- epilogue ----
    #pragma unroll
    for (int mt = 0; mt < 2; ++mt) {
        int r0 = rowBase + warpM * 32 + mt * 16 + tq;
        #pragma unroll
        for (int half = 0; half < 2; ++half) {
            int grow = r0 + half * 8;
            if (grow >= n) continue;
            float brs = biasRowScale ? __ldg(&biasRowScale[grow]) : 1.0f;
            #pragma unroll
            for (int nt = 0; nt < 8; ++nt) {
                int col = warpN * 64 + nt * 8 + tr * 2;
                float v0 = acc[mt][nt][half * 2];
                float v1 = acc[mt][nt][half * 2 + 1];
                if (bias) {
                    v0 += __ldg(&bias[col])     * brs;
                    v1 += __ldg(&bias[col + 1]) * brs;
                }
                if (Cadd) {
                    float2 ca = *(const float2*)&Cadd[grow * 128 + col];
                    v0 += ca.x; v1 += ca.y;
                }
                if (actMode == 1)      { v0 = mishf(v0); v1 = mishf(v1); }
                else if (actMode == 2) { v0 = mishf(mishf(v0)); v1 = mishf(mishf(v1)); }
                *(float2*)&C[grow * 128 + col] = make_float2(v0, v1);
            }
        }
    }
}

// ---------------------------------------------------------------------------
// Edge kernel: one warp per edge, vectorized global reds.
// ---------------------------------------------------------------------------
__global__ void __launch_bounds__(256) edge_kernel(
    const int*   __restrict__ ei,
    const int*   __restrict__ bt,
    const float* __restrict__ coords,
    const float* __restrict__ conv_w,
    const float* __restrict__ conv_b,
    const float* __restrict__ b_el,
    const float* __restrict__ x,
    const float4* __restrict__ Un, const float4* __restrict__ Vn,
    const float4* __restrict__ Ue, const float4* __restrict__ Ve,
    float4* Pn, float4* Pe, float4* T,
    float* s_arr, float* deg_arr, int E)
{
    int e = blockIdx.x * 8 + (threadIdx.x >> 5);
    if (e >= E) return;
    int lane = threadIdx.x & 31;

    int src = ei[e];
    int dst = ei[E + e];
    float norm = conv_w[bt[e]] + conv_b[0];

    float dx = coords[src * 3 + 0] - coords[dst * 3 + 0];
    float dy = coords[src * 3 + 1] - coords[dst * 3 + 1];
    float dz = coords[src * 3 + 2] - coords[dst * 3 + 2];
    float d2 = dx * dx + dy * dy + dz * dz;

    int di = dst * 32 + lane;
    int si = src * 32 + lane;

    {
        float4 u = Un[di], v = Vn[si], m;
        m.x = mishf(u.x + v.x); m.y = mishf(u.y + v.y);
        m.z = mishf(u.z + v.z); m.w = mishf(u.w + v.w);
        red_add_v4(&Pn[di], m);
    }
    {
        float4 u = Ue[di], v = Ve[si];
        float4 b = ((const float4*)b_el)[lane];
        float4 m;
        m.x = mishf(norm * (u.x + v.x) + b.x);
        m.y = mishf(norm * (u.y + v.y) + b.y);
        m.z = mishf(norm * (u.z + v.z) + b.z);
        m.w = mishf(norm * (u.w + v.w) + b.w);
        red_add_v4(&Pe[di], m);
    }
    {
        float4 xs = ((const float4*)x)[si];
        float4 m = make_float4(d2 * xs.x, d2 * xs.y, d2 * xs.z, d2 * xs.w);
        red_add_v4(&T[di], m);
    }
    if (lane == 0) {
        atomicAdd(&s_arr[dst], d2);
        atomicAdd(&deg_arr[dst], 1.0f);
    }
}

// ---------------------------------------------------------------------------
__global__ void attention_kernel(
    const float4* __restrict__ e0, const float4* __restrict__ e1,
    const float4* __restrict__ e2,
    const float4* __restrict__ f0, const float4* __restrict__ f1,
    const float4* __restrict__ f2,
    float4* __restrict__ att, int n4)
{
    int i = blockIdx.x * blockDim.x + threadIdx.x;
    if (i >= n4) return;
    float4 a0 = e0[i], a1 = e1[i], a2 = e2[i];
    float4 g0 = f0[i], g1 = f1[i], g2 = f2[i];
    float4 o;
    {
        float m = fmaxf(a0.x, fmaxf(a1.x, a2.x));
        float p0 = __expf(a0.x - m), p1 = __expf(a1.x - m), p2 = __expf(a2.x - m);
        o.x = __fdividef(p0 * g0.x + p1 * g1.x + p2 * g2.x, p0 + p1 + p2);
    }
    {
        float m = fmaxf(a0.y, fmaxf(a1.y, a2.y));
        float p0 = __expf(a0.y - m), p1 = __expf(a1.y - m), p2 = __expf(a2.y - m);
        o.y = __fdividef(p0 * g0.y + p1 * g1.y + p2 * g2.y, p0 + p1 + p2);
    }
    {
        float m = fmaxf(a0.z, fmaxf(a1.z, a2.z));
        float p0 = __expf(a0.z - m), p1 = __expf(a1.z - m), p2 = __expf(a2.z - m);
        o.z = __fdividef(p0 * g0.z + p1 * g1.z + p2 * g2.z, p0 + p1 + p2);
    }
    {
        float m = fmaxf(a0.w, fmaxf(a1.w, a2.w));
        float p0 = __expf(a0.w - m), p1 = __expf(a1.w - m), p2 = __expf(a2.w - m);
        o.w = __fdividef(p0 * g0.w + p1 * g1.w + p2 * g2.w, p0 + p1 + p2);
    }
    att[i] = o;
}

__global__ void bnstat_kernel(const float* __restrict__ H,
                              float* sum, float* sq, int n)
{
    int d  = threadIdx.x;
    int r0 = blockIdx.x * 256;
    int r1 = min(r0 + 256, n);
    float s = 0.f, q = 0.f;
    for (int r = r0; r < r1; ++r) {
        float v = H[r * 128 + d];
        s += v; q += v * v;
    }
    atomicAdd(&sum[d], s);
    atomicAdd(&sq[d],  q);
}

__global__ void final_kernel(const float* __restrict__ H,
                             const float* __restrict__ sum,
                             const float* __restrict__ sq,
                             const float* __restrict__ gamma,
                             const float* __restrict__ beta,
                             float* __restrict__ out, int n)
{
    int i = blockIdx.x * blockDim.x + threadIdx.x;
    if (i >= n * 128) return;
    int d = i & 127;
    float invn = 1.0f / (float)n;
    float mean = sum[d] * invn;
    float var  = sq[d] * invn - mean * mean;
    float v = (H[i] - mean) * rsqrtf(var + 1e-5f) * gamma[d] + beta[d];
    out[i] = mishf(v);
}

// ---------------------------------------------------------------------------
// Host launch
// ---------------------------------------------------------------------------
static float* symaddr(const void* sym) {
    void* p = nullptr;
    cudaGetSymbolAddress(&p, sym);
    return (float*)p;
}

#define GEMM_SMEM (4 * WELEMS * (int)sizeof(__nv_bfloat16))   // 139264 B

extern "C" void kernel_launch(void* const* d_in, const int* in_sizes, int n_in,
                              void* d_out, int out_size)
{
    const float* x       = (const float*)d_in[0];
    const float* coords  = (const float*)d_in[1];
    const int*   ei      = (const int*)  d_in[2];
    const int*   bt      = (const int*)  d_in[3];
    const float* W_nb    = (const float*)d_in[4];
    const float* b_nb    = (const float*)d_in[5];
    const float* W_nout  = (const float*)d_in[6];
    const float* b_nout  = (const float*)d_in[7];
    const float* conv_w  = (const float*)d_in[8];
    const float* conv_b  = (const float*)d_in[9];
    const float* W_el    = (const float*)d_in[10];
    const float* b_el    = (const float*)d_in[11];
    const float* W_eout  = (const float*)d_in[12];
    const float* b_eout  = (const float*)d_in[13];
    const float* W_coord = (const float*)d_in[14];
    const float* b_coord = (const float*)d_in[15];
    const float* W_pair  = (const float*)d_in[16];
    const float* b_pair  = (const float*)d_in[17];
    const float* W_sout  = (const float*)d_in[18];
    const float* b_sout  = (const float*)d_in[19];
    const float* W_init  = (const float*)d_in[20];
    const float* feat_lin= (const float*)d_in[21];
    const float* W_att   = (const float*)d_in[22];
    const float* W_agg   = (const float*)d_in[23];
    const float* gamma   = (const float*)d_in[24];
    const float* beta    = (const float*)d_in[25];

    const int N = in_sizes[0] / 128;
    const int E = in_sizes[2] / 2;

    static bool attrSet = false;
    if (!attrSet) {
        cudaFuncSetAttribute(mma_gemm,
            cudaFuncAttributeMaxDynamicSharedMemorySize, GEMM_SMEM);
        attrSet = true;
    }

    float* Un    = symaddr(g_b0);
    float* Vn    = symaddr(g_b1);
    float* Ue    = symaddr(g_b2);
    float* Ve    = symaddr(g_b3);
    float* Hini  = symaddr(g_b4);
    float* Einit = symaddr(g_b5);
    float* Pn    = symaddr(g_b6);
    float* Pe    = symaddr(g_b7);
    float* T     = symaddr(g_b8);
    float* Fn    = symaddr(g_b9);
    float* Fe    = symaddr(g_b10);
    float* Qp    = symaddr(g_b11);
    float* Q     = symaddr(g_b12);
    float* Fs    = symaddr(g_b13);
    float* sArr  = symaddr(g_s);
    float* dArr  = symaddr(g_deg);
    float* bnS   = symaddr(g_bnsum);
    float* bnQ   = symaddr(g_bnsq);
    float* E0 = Un; float* E1 = Vn; float* E2 = Ue;
    float* Att = Ve; float* Hagg = Hini; float* HR = Pn;

    const size_t vecBytes = (size_t)N * 128 * sizeof(float);
    cudaMemsetAsync(Pn,  0, vecBytes);
    cudaMemsetAsync(Pe,  0, vecBytes);
    cudaMemsetAsync(T,   0, vecBytes);
    cudaMemsetAsync(sArr, 0, N * sizeof(float));
    cudaMemsetAsync(dArr, 0, N * sizeof(float));
    cudaMemsetAsync(bnS, 0, 128 * sizeof(float));
    cudaMemsetAsync(bnQ, 0, 128 * sizeof(float));

    // Weight indices in g_wt:
    //  0 Wnb_top  1 Wnb_bot  2 Wel_top  3 Wel_bot  4 W_init  5 Watt_top
    //  6 W_nout   7 W_eout   8 Wc_top   9 Wc_bot  10 W_pair 11 Ws_top
    // 12 Ws_bot  13 fl0     14 fl1     15 fl2     16 Watt_bot 17 W_agg
    WPtrs wp;
    wp.p[0]  = W_nb;               wp.p[1]  = W_nb + 128 * 128;
    wp.p[2]  = W_el;               wp.p[3]  = W_el + 128 * 128;
    wp.p[4]  = W_init;             wp.p[5]  = W_att;
    wp.p[6]  = W_nout;             wp.p[7]  = W_eout;
    wp.p[8]  = W_coord;            wp.p[9]  = W_coord + 128 * 128;
    wp.p[10] = W_pair;             wp.p[11] = W_sout;
    wp.p[12] = W_sout + 128 * 128; wp.p[13] = feat_lin;
    wp.p[14] = feat_lin + 128 * 128; wp.p[15] = feat_lin + 2 * 128 * 128;
    wp.p[16] = W_att + 128 * 128;  wp.p[17] = W_agg;

    setup_weights<<<dim3(18, 8), 256>>>(wp);

    dim3 gb(256);
    dim3 gg((N + 127) / 128);

    // --- pre-phase projections (node space) ---
    mma_gemm<<<gg, gb, GEMM_SMEM>>>(x, 0, nullptr, -1, nullptr, b_nb,   nullptr, nullptr, Un,   N, 0);
    mma_gemm<<<gg, gb, GEMM_SMEM>>>(x, 1, nullptr, -1, nullptr, nullptr,nullptr, nullptr, Vn,   N, 0);
    mma_gemm<<<gg, gb, GEMM_SMEM>>>(x, 2, nullptr, -1, nullptr, nullptr,nullptr, nullptr, Ue,   N, 0);
    mma_gemm<<<gg, gb, GEMM_SMEM>>>(x, 3, nullptr, -1, nullptr, nullptr,nullptr, nullptr, Ve,   N, 0);
    mma_gemm<<<gg, gb, GEMM_SMEM>>>(x, 4, nullptr, -1, nullptr, nullptr,nullptr, nullptr, Hini, N, 2);
    mma_gemm<<<gg, gb, GEMM_SMEM>>>(Hini, 5, nullptr, -1, nullptr, nullptr, nullptr, nullptr, Einit, N, 0);

    // --- edge scatter phase ---
    edge_kernel<<<(E + 7) / 8, 256>>>(ei, bt, coords, conv_w, conv_b, b_el, x,
                                      (const float4*)Un, (const float4*)Vn,
                                      (const float4*)Ue, (const float4*)Ve,
                                      (float4*)Pn, (float4*)Pe, (float4*)T,
                                      sArr, dArr, E);

    // --- post-phase ---
    mma_gemm<<<gg, gb, GEMM_SMEM>>>(Pn, 6, nullptr, -1, nullptr, b_nout, nullptr, nullptr, Fn, N, 1);
    mma_gemm<<<gg, gb, GEMM_SMEM>>>(Pe, 7, nullptr, -1, nullptr, b_eout, nullptr, nullptr, Fe, N, 1);
    // Qpre = s ⊙ (x@Wc_top) + T@Wc_bot + deg ⊙ b_coord
    mma_gemm<<<gg, gb, GEMM_SMEM>>>(x, 8, T, 9, sArr, b_coord, dArr, nullptr, Qp, N, 0);
    mma_gemm<<<gg, gb, GEMM_SMEM>>>(Qp, 10, nullptr, -1, nullptr, b_pair, nullptr, nullptr, Q, N, 1);
    mma_gemm<<<gg, gb, GEMM_SMEM>>>(x, 11, Q, 12, nullptr, b_sout, nullptr, nullptr, Fs, N, 1);

    // attention logits per path: e_f = Einit + mish(mish(f @ FL_f)) @ Watt_bot
    mma_gemm<<<gg, gb, GEMM_SMEM>>>(Fn, 13, nullptr, -1, nullptr, nullptr, nullptr, nullptr, HR, N, 2);
    mma_gemm<<<gg, gb, GEMM_SMEM>>>(HR, 16, nullptr, -1, nullptr, nullptr, nullptr, Einit,   E0, N, 0);
    mma_gemm<<<gg, gb, GEMM_SMEM>>>(Fe, 14, nullptr, -1, nullptr, nullptr, nullptr, nullptr, HR, N, 2);
    mma_gemm<<<gg, gb, GEMM_SMEM>>>(HR, 16, nullptr, -1, nullptr, nullptr, nullptr, Einit,   E1, N, 0);
    mma_gemm<<<gg, gb, GEMM_SMEM>>>(Fs, 15, nullptr, -1, nullptr, nullptr, nullptr, nullptr, HR, N, 2);
    mma_gemm<<<gg, gb, GEMM_SMEM>>>(HR, 16, nullptr, -1, nullptr, nullptr, nullptr, Einit,   E2, N, 0);

    int n4 = N * 32;
    attention_kernel<<<(n4 + 255) / 256, 256>>>(
        (const float4*)E0, (const float4*)E1, (const float4*)E2,
        (const float4*)Fn, (const float4*)Fe, (const float4*)Fs,
        (float4*)Att, n4);

    mma_gemm<<<gg, gb, GEMM_SMEM>>>(Att, 17, nullptr, -1, nullptr, nullptr, nullptr, nullptr, Hagg, N, 0);

    bnstat_kernel<<<(N + 255) / 256, 128>>>(Hagg, bnS, bnQ, N);
    final_kernel<<<(N * 128 + 255) / 256, 256>>>(Hagg, bnS, bnQ, gamma, beta,
                                                 (float*)d_out, N);
}

// round 4
// speedup vs baseline: 1.5583x; 1.1301x over previous
#include <cuda_runtime.h>
#include <cuda_bf16.h>
#include <cstdint>

// ---------------------------------------------------------------------------
// MultiPathLayer: N=50000 nodes, E=800000 edges, D=128.
// GEMMs via mma.sync bf16 (split-bf16, fp32 accuracy), ldmatrix fragment
// loads, cp.async weight prefetch, multi-job batching, 2 CTAs/SM.
// ---------------------------------------------------------------------------

#define NMAX 50000
#define DDIM 128
#define WPAD 136           // padded row length in bf16 elems — LDSM conflict-free
#define WELEMS (128 * WPAD)

__device__ float4 g_b0 [NMAX * 32];   // Un   -> later E0
__device__ float4 g_b1 [NMAX * 32];   // Vn   -> later E1
__device__ float4 g_b2 [NMAX * 32];   // Ue   -> later E2
__device__ float4 g_b3 [NMAX * 32];   // Ve   -> later Att
__device__ float4 g_b4 [NMAX * 32];   // Hini -> later Hagg
__device__ float4 g_b5 [NMAX * 32];   // Einit
__device__ float4 g_b6 [NMAX * 32];   // Pn   -> later HR0
__device__ float4 g_b7 [NMAX * 32];   // Pe
__device__ float4 g_b8 [NMAX * 32];   // T
__device__ float4 g_b9 [NMAX * 32];   // Fn
__device__ float4 g_b10[NMAX * 32];   // Fe
__device__ float4 g_b11[NMAX * 32];   // Qp -> later HR1
__device__ float4 g_b12[NMAX * 32];   // Q  -> later HR2
__device__ float4 g_b13[NMAX * 32];   // Fs
__device__ float  g_s[NMAX];
__device__ float  g_deg[NMAX];
__device__ float  g_bnsum[DDIM];
__device__ float  g_bnsq[DDIM];

// Pre-converted weights: [weight][hi/lo][n*WPAD + k] (B operand layout [n][k]).
__device__ __align__(16) __nv_bfloat16 g_wt[18][2][WELEMS];

__device__ __forceinline__ float mishf(float x) {
    float e  = __expf(fminf(x, 30.0f));
    float t  = 1.0f + e;
    float t2 = t * t;
    return x * __fdividef(t2 - 1.0f, t2 + 1.0f);
}

__device__ __forceinline__ void red_add_v4(float4* p, float4 v) {
    asm volatile("red.global.add.v4.f32 [%0], {%1,%2,%3,%4};"
                 :: "l"(p), "f"(v.x), "f"(v.y), "f"(v.z), "f"(v.w)
                 : "memory");
}

__device__ __forceinline__ uint32_t smem_u32(const void* p) {
    uint32_t a;
    asm("{ .reg .u64 t; cvta.to.shared.u64 t, %1; cvt.u32.u64 %0, t; }"
        : "=r"(a) : "l"(p));
    return a;
}

__device__ __forceinline__ void mma_bf16(float* c, const uint32_t* a,
                                         const uint32_t* b) {
    asm volatile(
        "mma.sync.aligned.m16n8k16.row.col.f32.bf16.bf16.f32 "
        "{%0,%1,%2,%3}, {%4,%5,%6,%7}, {%8,%9}, {%0,%1,%2,%3};"
        : "+f"(c[0]), "+f"(c[1]), "+f"(c[2]), "+f"(c[3])
        : "r"(a[0]), "r"(a[1]), "r"(a[2]), "r"(a[3]), "r"(b[0]), "r"(b[1]));
}

__device__ __forceinline__ void ldsm4(uint32_t* r, uint32_t addr) {
    asm volatile("ldmatrix.sync.aligned.m8n8.x4.shared.b16 {%0,%1,%2,%3}, [%4];"
        : "=r"(r[0]), "=r"(r[1]), "=r"(r[2]), "=r"(r[3]) : "r"(addr));
}

__device__ __forceinline__ void cp_async16(uint32_t saddr, const void* g) {
    asm volatile("cp.async.cg.shared.global [%0], [%1], 16;"
                 :: "r"(saddr), "l"(g) : "memory");
}

// ---------------------------------------------------------------------------
// Weight setup: W[128,128] fp32 (row-major [k][n]) -> transposed padded hi/lo
// bf16 in g_wt[w].  grid = (18, 8), 256 threads.
// ---------------------------------------------------------------------------
struct WPtrs { const float* p[18]; };

__global__ void setup_weights(WPtrs wp)
{
    int w = blockIdx.x;
    const float* W = wp.p[w];
    __nv_bfloat16* hi = g_wt[w][0];
    __nv_bfloat16* lo = g_wt[w][1];
    for (int it = 0; it < 8; ++it) {
        int idx = blockIdx.y * 2048 + it * 256 + threadIdx.x;
        int k = idx >> 7;
        int n = idx & 127;
        float v = W[idx];
        __nv_bfloat16 h = __float2bfloat16(v);
        __nv_bfloat16 l = __float2bfloat16(v - __bfloat162float(h));
        hi[n * WPAD + k] = h;
        lo[n * WPAD + k] = l;
    }
}

// ---------------------------------------------------------------------------
// Batched mma.sync GEMM.
// Each job: C[n,128] = act( rowScale⊙(A@W[w1]) + (A2@W[w2])
//                           + biasRowScale⊙bias + Cadd )
// CTA tile: 64 rows x 128 cols, 256 threads (8 warps as 2M x 4N, 32x32 each).
// smem layout (bf16 elems): A_hi[0,8704) A_lo[8704,17408)
//                           B_hi[17408,34816) B_lo[34816,52224)
// ---------------------------------------------------------------------------
struct Job {
    const float* A; const float* A2;
    const float* rowScale; const float* bias;
    const float* biasRowScale; const float* Cadd;
    float* C;
    int w1, w2, actMode, convertA;
};
struct JobList { Job j[5]; int count; };

__global__ void __launch_bounds__(256, 2) mma_gemm(JobList jl, int n)
{
    extern __shared__ __nv_bfloat16 sm[];
    const int tid  = threadIdx.x;
    const int wid  = tid >> 5;
    const int lane = tid & 31;
    const int tq = lane >> 2;
    const int tr = lane & 3;
    const int warpM = wid >> 2;     // 0..1
    const int warpN = wid & 3;      // 0..3
    const int rowBase = blockIdx.x * 64;

    const uint32_t smBase  = smem_u32(sm);
    const uint32_t aHiAddr = smBase;
    const uint32_t aLoAddr = smBase + 17408;
    const uint32_t bHiAddr = smBase + 34816;
    const uint32_t bLoAddr = smBase + 69632;

    // per-lane ldmatrix offsets (bytes)
    const uint32_t aoff0 = ((warpM * 32 + (lane & 15)) * WPAD + (lane >> 4) * 8) * 2;
    const uint32_t aoff1 = aoff0 + 16 * WPAD * 2;
    const int bRow = warpN * 32 + ((lane >> 4) << 3) + (lane & 7);
    const uint32_t boff0 = (bRow * WPAD + ((lane >> 3) & 1) * 8) * 2;
    const uint32_t boff1 = boff0 + 16 * WPAD * 2;

    for (int ji = 0; ji < jl.count; ++ji) {
        const Job J = jl.j[ji];

        float acc[2][4][4];
        #pragma unroll
        for (int i = 0; i < 2; ++i)
            #pragma unroll
            for (int j = 0; j < 4; ++j)
                #pragma unroll
                for (int q = 0; q < 4; ++q) acc[i][j][q] = 0.0f;

        const int passes = (J.A2 != nullptr) ? 2 : 1;
        for (int p = 0; p < passes; ++p) {
            const float* Ap  = p ? J.A2 : J.A;
            const float* rsp = p ? nullptr : J.rowScale;
            const bool doConv = (p == 1) || (J.convertA != 0);
            const int  w = p ? J.w2 : J.w1;

            __syncthreads();   // previous mainloop/B done with smem

            // --- B prefetch: hi+lo 69632 B via cp.async ---
            {
                const char* src = (const char*)g_wt[w] + tid * 16;
                uint32_t dst = bHiAddr + tid * 16;
                #pragma unroll
                for (int it = 0; it < 17; ++it)
                    cp_async16(dst + it * 4096, src + it * 4096);
                asm volatile("cp.async.commit_group;" ::: "memory");
            }

            // --- A tile: 64x128 fp32 -> hi/lo bf16 (overlaps B prefetch) ---
            if (doConv) {
                #pragma unroll
                for (int it = 0; it < 8; ++it) {
                    int idx = tid + (it << 8);
                    int row = idx >> 5;
                    int c4  = idx & 31;
                    int grow = rowBase + row;
                    float4 v = make_float4(0.f, 0.f, 0.f, 0.f);
                    if (grow < n) {
                        v = *(const float4*)&Ap[grow * 128 + c4 * 4];
                        if (rsp) {
                            float s = __ldg(&rsp[grow]);
                            v.x *= s; v.y *= s; v.z *= s; v.w *= s;
                        }
                    }
                    __nv_bfloat16 hx = __float2bfloat16(v.x);
                    __nv_bfloat16 hy = __float2bfloat16(v.y);
                    __nv_bfloat16 hz = __float2bfloat16(v.z);
                    __nv_bfloat16 hw = __float2bfloat16(v.w);
                    __nv_bfloat162 h01; h01.x = hx; h01.y = hy;
                    __nv_bfloat162 h23; h23.x = hz; h23.y = hw;
                    __nv_bfloat162 l01, l23;
                    l01.x = __float2bfloat16(v.x - __bfloat162float(hx));
                    l01.y = __float2bfloat16(v.y - __bfloat162float(hy));
                    l23.x = __float2bfloat16(v.z - __bfloat162float(hz));
                    l23.y = __float2bfloat16(v.w - __bfloat162float(hw));
                    int o = row * WPAD + c4 * 4;
                    *(__nv_bfloat162*)&sm[o]            = h01;
                    *(__nv_bfloat162*)&sm[o + 2]        = h23;
                    *(__nv_bfloat162*)&sm[8704 + o]     = l01;
                    *(__nv_bfloat162*)&sm[8704 + o + 2] = l23;
                }
            }
            asm volatile("cp.async.wait_group 0;" ::: "memory");
            __syncthreads();

            // --- mainloop: 3 split terms x 8 k-steps ---
            #pragma unroll
            for (int sel = 0; sel < 3; ++sel) {
                const uint32_t aB = (sel == 1) ? aLoAddr : aHiAddr;
                const uint32_t bB = (sel == 2) ? bLoAddr : bHiAddr;
                #pragma unroll
                for (int kk = 0; kk < 8; ++kk) {
                    uint32_t ko = kk * 32;
                    uint32_t a0[4], a1[4], b0[4], b1[4];
                    ldsm4(a0, aB + aoff0 + ko);
                    ldsm4(a1, aB + aoff1 + ko);
                    ldsm4(b0, bB + boff0 + ko);
                    ldsm4(b1, bB + boff1 + ko);
                    mma_bf16(acc[0][0], a0, &b0[0]);
                    mma_bf16(acc[0][1], a0, &b0[2]);
                    mma_bf16(acc[0][2], a0, &b1[0]);
                    mma_bf16(acc[0][3], a0, &b1[2]);
                    mma_bf16(acc[1][0], a1, &b0[0]);
                    mma_bf16(acc[1][1], a1, &b0[2]);
                    mma_bf16(acc[1][2], a1, &b1[0]);
                    mma_bf16(acc[1][3], a1, &b1[2]);
                }
            }
        }

        // --- epilogue ---
        #pragma unroll
        for (int mt = 0; mt < 2; ++mt) {
            #pragma unroll
            for (int half = 0; half < 2; ++half) {
                int grow = rowBase + warpM * 32 + mt * 16 + tq + half * 8;
                if (grow >= n) continue;
                float brs = J.biasRowScale ? __ldg(&J.biasRowScale[grow]) : 1.0f;
                #pragma unroll
                for (int nt = 0; nt < 4; ++nt) {
                    int col = warpN * 32 + nt * 8 + tr * 2;
                    float v0 = acc[mt][nt][half * 2];
                    float v1 = acc[mt][nt][half * 2 + 1];
                    if (J.bias) {
                        v0 += __ldg(&J.bias[col])     * brs;
                        v1 += __ldg(&J.bias[col + 1]) * brs;
                    }
                    if (J.Cadd) {
                        float2 ca = *(const float2*)&J.Cadd[grow * 128 + col];
                        v0 += ca.x; v1 += ca.y;
                    }
                    if (J.actMode == 1)      { v0 = mishf(v0); v1 = mishf(v1); }
                    else if (J.actMode == 2) { v0 = mishf(mishf(v0)); v1 = mishf(mishf(v1)); }
                    *(float2*)&J.C[grow * 128 + col] = make_float2(v0, v1);
                }
            }
        }
    }
}

// ---------------------------------------------------------------------------
// Edge kernel: one warp per edge, vectorized global reds.
// ---------------------------------------------------------------------------
__global__ void __launch_bounds__(256) edge_kernel(
    const int*   __restrict__ ei,
    const int*   __restrict__ bt,
    const float* __restrict__ coords,
    const float* __restrict__ conv_w,
    const float* __restrict__ conv_b,
    const float* __restrict__ b_el,
    const float* __restrict__ x,
    const float4* __restrict__ Un, const float4* __restrict__ Vn,
    const float4* __restrict__ Ue, const float4* __restrict__ Ve,
    float4* Pn, float4* Pe, float4* T,
    float* s_arr, float* deg_arr, int E)
{
    int e = blockIdx.x * 8 + (threadIdx.x >> 5);
    if (e >= E) return;
    int lane = threadIdx.x & 31;

    int src = ei[e];
    int dst = ei[E + e];
    float norm = conv_w[bt[e]] + conv_b[0];

    float dx = coords[src * 3 + 0] - coords[dst * 3 + 0];
    float dy = coords[src * 3 + 1] - coords[dst * 3 + 1];
    float dz = coords[src * 3 + 2] - coords[dst * 3 + 2];
    float d2 = dx * dx + dy * dy + dz * dz;

    int di = dst * 32 + lane;
    int si = src * 32 + lane;

    {
        float4 u = Un[di], v = Vn[si], m;
        m.x = mishf(u.x + v.x); m.y = mishf(u.y + v.y);
        m.z = mishf(u.z + v.z); m.w = mishf(u.w + v.w);
        red_add_v4(&Pn[di], m);
    }
    {
        float4 u = Ue[di], v = Ve[si];
        float4 b = ((const float4*)b_el)[lane];
        float4 m;
        m.x = mishf(norm * (u.x + v.x) + b.x);
        m.y = mishf(norm * (u.y + v.y) + b.y);
        m.z = mishf(norm * (u.z + v.z) + b.z);
        m.w = mishf(norm * (u.w + v.w) + b.w);
        red_add_v4(&Pe[di], m);
    }
    {
        float4 xs = ((const float4*)x)[si];
        float4 m = make_float4(d2 * xs.x, d2 * xs.y, d2 * xs.z, d2 * xs.w);
        red_add_v4(&T[di], m);
    }
    if (lane == 0) {
        atomicAdd(&s_arr[dst], d2);
        atomicAdd(&deg_arr[dst], 1.0f);
    }
}

// ---------------------------------------------------------------------------
__global__ void attention_kernel(
    const float4* __restrict__ e0, const float4* __restrict__ e1,
    const float4* __restrict__ e2,
    const float4* __restrict__ f0, const float4* __restrict__ f1,
    const float4* __restrict__ f2,
    float4* __restrict__ att, int n4)
{
    int i = blockIdx.x * blockDim.x + threadIdx.x;
    if (i >= n4) return;
    float4 a0 = e0[i], a1 = e1[i], a2 = e2[i];
    float4 g0 = f0[i], g1 = f1[i], g2 = f2[i];
    float4 o;
    {
        float m = fmaxf(a0.x, fmaxf(a1.x, a2.x));
        float p0 = __expf(a0.x - m), p1 = __expf(a1.x - m), p2 = __expf(a2.x - m);
        o.x = __fdividef(p0 * g0.x + p1 * g1.x + p2 * g2.x, p0 + p1 + p2);
    }
    {
        float m = fmaxf(a0.y, fmaxf(a1.y, a2.y));
        float p0 = __expf(a0.y - m), p1 = __expf(a1.y - m), p2 = __expf(a2.y - m);
        o.y = __fdividef(p0 * g0.y + p1 * g1.y + p2 * g2.y, p0 + p1 + p2);
    }
    {
        float m = fmaxf(a0.z, fmaxf(a1.z, a2.z));
        float p0 = __expf(a0.z - m), p1 = __expf(a1.z - m), p2 = __expf(a2.z - m);
        o.z = __fdividef(p0 * g0.z + p1 * g1.z + p2 * g2.z, p0 + p1 + p2);
    }
    {
        float m = fmaxf(a0.w, fmaxf(a1.w, a2.w));
        float p0 = __expf(a0.w - m), p1 = __expf(a1.w - m), p2 = __expf(a2.w - m);
        o.w = __fdividef(p0 * g0.w + p1 * g1.w + p2 * g2.w, p0 + p1 + p2);
    }
    att[i] = o;
}

__global__ void bnstat_kernel(const float* __restrict__ H,
                              float* sum, float* sq, int n)
{
    int d  = threadIdx.x;
    int r0 = blockIdx.x * 256;
    int r1 = min(r0 + 256, n);
    float s = 0.f, q = 0.f;
    for (int r = r0; r < r1; ++r) {
        float v = H[r * 128 + d];
        s += v; q += v * v;
    }
    atomicAdd(&sum[d], s);
    atomicAdd(&sq[d],  q);
}

__global__ void final_kernel(const float* __restrict__ H,
                             const float* __restrict__ sum,
                             const float* __restrict__ sq,
                             const float* __restrict__ gamma,
                             const float* __restrict__ beta,
                             float* __restrict__ out, int n)
{
    int i = blockIdx.x * blockDim.x + threadIdx.x;
    if (i >= n * 128) return;
    int d = i & 127;
    float invn = 1.0f / (float)n;
    float mean = sum[d] * invn;
    float var  = sq[d] * invn - mean * mean;
    float v = (H[i] - mean) * rsqrtf(var + 1e-5f) * gamma[d] + beta[d];
    out[i] = mishf(v);
}

// ---------------------------------------------------------------------------
// Host launch
// ---------------------------------------------------------------------------
static float* symaddr(const void* sym) {
    void* p = nullptr;
    cudaGetSymbolAddress(&p, sym);
    return (float*)p;
}

#define GEMM_SMEM 104448

static Job mkjob(const float* A, int w1, float* C, int act,
                 const float* bias = nullptr, int convertA = 1,
                 const float* A2 = nullptr, int w2 = -1,
                 const float* rowScale = nullptr,
                 const float* brs = nullptr, const float* Cadd = nullptr)
{
    Job j;
    j.A = A; j.A2 = A2; j.rowScale = rowScale; j.bias = bias;
    j.biasRowScale = brs; j.Cadd = Cadd; j.C = C;
    j.w1 = w1; j.w2 = w2; j.actMode = act; j.convertA = convertA;
    return j;
}

extern "C" void kernel_launch(void* const* d_in, const int* in_sizes, int n_in,
                              void* d_out, int out_size)
{
    const float* x       = (const float*)d_in[0];
    const float* coords  = (const float*)d_in[1];
    const int*   ei      = (const int*)  d_in[2];
    const int*   bt      = (const int*)  d_in[3];
    const float* W_nb    = (const float*)d_in[4];
    const float* b_nb    = (const float*)d_in[5];
    const float* W_nout  = (const float*)d_in[6];
    const float* b_nout  = (const float*)d_in[7];
    const float* conv_w  = (const float*)d_in[8];
    const float* conv_b  = (const float*)d_in[9];
    const float* W_el    = (const float*)d_in[10];
    const float* b_el    = (const float*)d_in[11];
    const float* W_eout  = (const float*)d_in[12];
    const float* b_eout  = (const float*)d_in[13];
    const float* W_coord = (const float*)d_in[14];
    const float* b_coord = (const float*)d_in[15];
    const float* W_pair  = (const float*)d_in[16];
    const float* b_pair  = (const float*)d_in[17];
    const float* W_sout  = (const float*)d_in[18];
    const float* b_sout  = (const float*)d_in[19];
    const float* W_init  = (const float*)d_in[20];
    const float* feat_lin= (const float*)d_in[21];
    const float* W_att   = (const float*)d_in[22];
    const float* W_agg   = (const float*)d_in[23];
    const float* gamma   = (const float*)d_in[24];
    const float* beta    = (const float*)d_in[25];

    const int N = in_sizes[0] / 128;
    const int E = in_sizes[2] / 2;

    static bool attrSet = false;
    if (!attrSet) {
        cudaFuncSetAttribute(mma_gemm,
            cudaFuncAttributeMaxDynamicSharedMemorySize, GEMM_SMEM);
        attrSet = true;
    }

    float* Un    = symaddr(g_b0);
    float* Vn    = symaddr(g_b1);
    float* Ue    = symaddr(g_b2);
    float* Ve    = symaddr(g_b3);
    float* Hini  = symaddr(g_b4);
    float* Einit = symaddr(g_b5);
    float* Pn    = symaddr(g_b6);
    float* Pe    = symaddr(g_b7);
    float* T     = symaddr(g_b8);
    float* Fn    = symaddr(g_b9);
    float* Fe    = symaddr(g_b10);
    float* Qp    = symaddr(g_b11);
    float* Q     = symaddr(g_b12);
    float* Fs    = symaddr(g_b13);
    float* sArr  = symaddr(g_s);
    float* dArr  = symaddr(g_deg);
    float* bnS   = symaddr(g_bnsum);
    float* bnQ   = symaddr(g_bnsq);
    float* E0 = Un; float* E1 = Vn; float* E2 = Ue;
    float* Att = Ve; float* Hagg = Hini;
    float* HR0 = Pn; float* HR1 = Qp; float* HR2 = Q;

    const size_t vecBytes = (size_t)N * 128 * sizeof(float);
    cudaMemsetAsync(Pn,  0, vecBytes);
    cudaMemsetAsync(Pe,  0, vecBytes);
    cudaMemsetAsync(T,   0, vecBytes);
    cudaMemsetAsync(sArr, 0, N * sizeof(float));
    cudaMemsetAsync(dArr, 0, N * sizeof(float));
    cudaMemsetAsync(bnS, 0, 128 * sizeof(float));
    cudaMemsetAsync(bnQ, 0, 128 * sizeof(float));

    // Weight indices in g_wt:
    //  0 Wnb_top  1 Wnb_bot  2 Wel_top  3 Wel_bot  4 W_init  5 Watt_top
    //  6 W_nout   7 W_eout   8 Wc_top   9 Wc_bot  10 W_pair 11 Ws_top
    // 12 Ws_bot  13 fl0     14 fl1     15 fl2     16 Watt_bot 17 W_agg
    WPtrs wp;
    wp.p[0]  = W_nb;               wp.p[1]  = W_nb + 128 * 128;
    wp.p[2]  = W_el;               wp.p[3]  = W_el + 128 * 128;
    wp.p[4]  = W_init;             wp.p[5]  = W_att;
    wp.p[6]  = W_nout;             wp.p[7]  = W_eout;
    wp.p[8]  = W_coord;            wp.p[9]  = W_coord + 128 * 128;
    wp.p[10] = W_pair;             wp.p[11] = W_sout;
    wp.p[12] = W_sout + 128 * 128; wp.p[13] = feat_lin;
    wp.p[14] = feat_lin + 128 * 128; wp.p[15] = feat_lin + 2 * 128 * 128;
    wp.p[16] = W_att + 128 * 128;  wp.p[17] = W_agg;

    setup_weights<<<dim3(18, 8), 256>>>(wp);

    dim3 gb(256);
    dim3 gg((N + 63) / 64);

    JobList jl;

    // --- G1: 5 projections sharing A=x (convert once) ---
    jl.count = 5;
    jl.j[0] = mkjob(x, 0, Un,   0, b_nb, 1);
    jl.j[1] = mkjob(x, 1, Vn,   0, nullptr, 0);
    jl.j[2] = mkjob(x, 2, Ue,   0, nullptr, 0);
    jl.j[3] = mkjob(x, 3, Ve,   0, nullptr, 0);
    jl.j[4] = mkjob(x, 4, Hini, 2, nullptr, 0);
    mma_gemm<<<gg, gb, GEMM_SMEM>>>(jl, N);

    // --- G2: Einit = Hini @ Watt_top ---
    jl.count = 1;
    jl.j[0] = mkjob(Hini, 5, Einit, 0);
    mma_gemm<<<gg, gb, GEMM_SMEM>>>(jl, N);

    // --- edge scatter phase ---
    edge_kernel<<<(E + 7) / 8, 256>>>(ei, bt, coords, conv_w, conv_b, b_el, x,
                                      (const float4*)Un, (const float4*)Vn,
                                      (const float4*)Ue, (const float4*)Ve,
                                      (float4*)Pn, (float4*)Pe, (float4*)T,
                                      sArr, dArr, E);

    // --- G3: Fn, Fe, Qp ---
    jl.count = 3;
    jl.j[0] = mkjob(Pn, 6, Fn, 1, b_nout, 1);
    jl.j[1] = mkjob(Pe, 7, Fe, 1, b_eout, 1);
    jl.j[2] = mkjob(x, 8, Qp, 0, b_coord, 1, T, 9, sArr, dArr);
    mma_gemm<<<gg, gb, GEMM_SMEM>>>(jl, N);

    // --- G4: Q = mish(Qp @ W_pair + b_pair) ---
    jl.count = 1;
    jl.j[0] = mkjob(Qp, 10, Q, 1, b_pair, 1);
    mma_gemm<<<gg, gb, GEMM_SMEM>>>(jl, N);

    // --- G5: Fs = mish(x@Ws_top + Q@Ws_bot + b_sout) ---
    jl.count = 1;
    jl.j[0] = mkjob(x, 11, Fs, 1, b_sout, 1, Q, 12);
    mma_gemm<<<gg, gb, GEMM_SMEM>>>(jl, N);

    // --- G6: HR_f = mish(mish(F_f @ FL_f)) ---
    jl.count = 3;
    jl.j[0] = mkjob(Fn, 13, HR0, 2);
    jl.j[1] = mkjob(Fe, 14, HR1, 2);
    jl.j[2] = mkjob(Fs, 15, HR2, 2);
    mma_gemm<<<gg, gb, GEMM_SMEM>>>(jl, N);

    // --- G7: E_f = HR_f @ Watt_bot + Einit ---
    jl.count = 3;
    jl.j[0] = mkjob(HR0, 16, E0, 0, nullptr, 1, nullptr, -1, nullptr, nullptr, Einit);
    jl.j[1] = mkjob(HR1, 16, E1, 0, nullptr, 1, nullptr, -1, nullptr, nullptr, Einit);
    jl.j[2] = mkjob(HR2, 16, E2, 0, nullptr, 1, nullptr, -1, nullptr, nullptr, Einit);
    mma_gemm<<<gg, gb, GEMM_SMEM>>>(jl, N);

    int n4 = N * 32;
    attention_kernel<<<(n4 + 255) / 256, 256>>>(
        (const float4*)E0, (const float4*)E1, (const float4*)E2,
        (const float4*)Fn, (const float4*)Fe, (const float4*)Fs,
        (float4*)Att, n4);

    // --- G8: Hagg = Att @ W_agg ---
    jl.count = 1;
    jl.j[0] = mkjob(Att, 17, Hagg, 0);
    mma_gemm<<<gg, gb, GEMM_SMEM>>>(jl, N);

    bnstat_kernel<<<(N + 255) / 256, 128>>>(Hagg, bnS, bnQ, N);
    final_kernel<<<(N * 128 + 255) / 256, 256>>>(Hagg, bnS, bnQ, gamma, beta,
                                                 (float*)d_out, N);
}

// round 5
// speedup vs baseline: 1.5719x; 1.0087x over previous
#include <cuda_runtime.h>
#include <cuda_bf16.h>
#include <cstdint>

// ---------------------------------------------------------------------------
// MultiPathLayer: N=50000 nodes, E=800000 edges, D=128.
// GEMMs via mma.sync bf16 (split-bf16, fp32 accuracy), ldmatrix, cp.async,
// smem chain-fusion of GEMM sequences. Edge phase split into 3 L2-resident
// passes with vectorized global reductions.
// ---------------------------------------------------------------------------

#define NMAX 50000
#define DDIM 128
#define WPAD 136           // padded row length in bf16 elems — LDSM conflict-free
#define WELEMS (128 * WPAD)

__device__ float4 g_b0 [NMAX * 32];   // Un   -> later E0
__device__ float4 g_b1 [NMAX * 32];   // Vn   -> later E1
__device__ float4 g_b2 [NMAX * 32];   // Ue   -> later E2
__device__ float4 g_b3 [NMAX * 32];   // Ve   -> later Att
__device__ float4 g_b4 [NMAX * 32];   // Hagg
__device__ float4 g_b5 [NMAX * 32];   // Einit
__device__ float4 g_b6 [NMAX * 32];   // Pn
__device__ float4 g_b7 [NMAX * 32];   // Pe
__device__ float4 g_b8 [NMAX * 32];   // T
__device__ float4 g_b9 [NMAX * 32];   // Fn
__device__ float4 g_b10[NMAX * 32];   // Fe
__device__ float4 g_b11[NMAX * 32];   // Qp
__device__ float4 g_b13[NMAX * 32];   // Fs
__device__ float  g_s[NMAX];
__device__ float  g_deg[NMAX];
__device__ float  g_bnsum[DDIM];
__device__ float  g_bnsq[DDIM];

// Pre-converted weights: [weight][hi/lo][n*WPAD + k] (B operand layout [n][k]).
__device__ __align__(16) __nv_bfloat16 g_wt[18][2][WELEMS];

__device__ __forceinline__ float mishf(float x) {
    float e  = __expf(fminf(x, 30.0f));
    float t  = 1.0f + e;
    float t2 = t * t;
    return x * __fdividef(t2 - 1.0f, t2 + 1.0f);
}

__device__ __forceinline__ void red_add_v4(float4* p, float4 v) {
    asm volatile("red.global.add.v4.f32 [%0], {%1,%2,%3,%4};"
                 :: "l"(p), "f"(v.x), "f"(v.y), "f"(v.z), "f"(v.w)
                 : "memory");
}

__device__ __forceinline__ uint32_t smem_u32(const void* p) {
    uint32_t a;
    asm("{ .reg .u64 t; cvta.to.shared.u64 t, %1; cvt.u32.u64 %0, t; }"
        : "=r"(a) : "l"(p));
    return a;
}

__device__ __forceinline__ void mma_bf16(float* c, const uint32_t* a,
                                         const uint32_t* b) {
    asm volatile(
        "mma.sync.aligned.m16n8k16.row.col.f32.bf16.bf16.f32 "
        "{%0,%1,%2,%3}, {%4,%5,%6,%7}, {%8,%9}, {%0,%1,%2,%3};"
        : "+f"(c[0]), "+f"(c[1]), "+f"(c[2]), "+f"(c[3])
        : "r"(a[0]), "r"(a[1]), "r"(a[2]), "r"(a[3]), "r"(b[0]), "r"(b[1]));
}

__device__ __forceinline__ void ldsm4(uint32_t* r, uint32_t addr) {
    asm volatile("ldmatrix.sync.aligned.m8n8.x4.shared.b16 {%0,%1,%2,%3}, [%4];"
        : "=r"(r[0]), "=r"(r[1]), "=r"(r[2]), "=r"(r[3]) : "r"(addr));
}

__device__ __forceinline__ void cp_async16(uint32_t saddr, const void* g) {
    asm volatile("cp.async.cg.shared.global [%0], [%1], 16;"
                 :: "r"(saddr), "l"(g) : "memory");
}

// ---------------------------------------------------------------------------
// Weight setup.
// ---------------------------------------------------------------------------
struct WPtrs { const float* p[18]; };

__global__ void setup_weights(WPtrs wp)
{
    int w = blockIdx.x;
    const float* W = wp.p[w];
    __nv_bfloat16* hi = g_wt[w][0];
    __nv_bfloat16* lo = g_wt[w][1];
    for (int it = 0; it < 8; ++it) {
        int idx = blockIdx.y * 2048 + it * 256 + threadIdx.x;
        int k = idx >> 7;
        int n = idx & 127;
        float v = W[idx];
        __nv_bfloat16 h = __float2bfloat16(v);
        __nv_bfloat16 l = __float2bfloat16(v - __bfloat162float(h));
        hi[n * WPAD + k] = h;
        lo[n * WPAD + k] = l;
    }
}

// ---------------------------------------------------------------------------
// Batched / chain-fused mma.sync GEMM.
// Each job: T = act( rowScale⊙(A@W[w1]) + (A2@W[w2]) + biasRowScale⊙bias
//                    + Cadd )
//   chainOut=0: write T to C (global)
//   chainOut=1: write T into the A-operand smem (bf16 hi/lo) — the next job
//               with convertA=0 consumes it as its A.
// CTA tile: 64 rows x 128 cols, 256 threads (8 warps as 2M x 4N).
// ---------------------------------------------------------------------------
struct Job {
    const float* A; const float* A2;
    const float* rowScale; const float* bias;
    const float* biasRowScale; const float* Cadd;
    float* C;
    int w1, w2, actMode, convertA, chainOut;
};
struct JobList { Job j[6]; int count; };

__global__ void __launch_bounds__(256, 2) mma_gemm(JobList jl, int n)
{
    extern __shared__ __nv_bfloat16 sm[];
    const int tid  = threadIdx.x;
    const int wid  = tid >> 5;
    const int lane = tid & 31;
    const int tq = lane >> 2;
    const int tr = lane & 3;
    const int warpM = wid >> 2;     // 0..1
    const int warpN = wid & 3;      // 0..3
    const int rowBase = blockIdx.x * 64;

    const uint32_t smBase  = smem_u32(sm);
    const uint32_t aHiAddr = smBase;
    const uint32_t aLoAddr = smBase + 17408;
    const uint32_t bHiAddr = smBase + 34816;
    const uint32_t bLoAddr = smBase + 69632;

    const uint32_t aoff0 = ((warpM * 32 + (lane & 15)) * WPAD + (lane >> 4) * 8) * 2;
    const uint32_t aoff1 = aoff0 + 16 * WPAD * 2;
    const int bRow = warpN * 32 + ((lane >> 4) << 3) + (lane & 7);
    const uint32_t boff0 = (bRow * WPAD + ((lane >> 3) & 1) * 8) * 2;
    const uint32_t boff1 = boff0 + 16 * WPAD * 2;

    for (int ji = 0; ji < jl.count; ++ji) {
        const Job J = jl.j[ji];

        float acc[2][4][4];
        #pragma unroll
        for (int i = 0; i < 2; ++i)
            #pragma unroll
            for (int j = 0; j < 4; ++j)
                #pragma unroll
                for (int q = 0; q < 4; ++q) acc[i][j][q] = 0.0f;

        const int passes = (J.A2 != nullptr) ? 2 : 1;
        for (int p = 0; p < passes; ++p) {
            const float* Ap  = p ? J.A2 : J.A;
            const float* rsp = p ? nullptr : J.rowScale;
            const bool doConv = (p == 1) || (J.convertA != 0);
            const int  w = p ? J.w2 : J.w1;

            __syncthreads();   // previous mainloop / chain writes done

            // --- B prefetch: hi+lo 69632 B via cp.async ---
            {
                const char* src = (const char*)g_wt[w] + tid * 16;
                uint32_t dst = bHiAddr + tid * 16;
                #pragma unroll
                for (int it = 0; it < 17; ++it)
                    cp_async16(dst + it * 4096, src + it * 4096);
                asm volatile("cp.async.commit_group;" ::: "memory");
            }

            // --- A tile: 64x128 fp32 -> hi/lo bf16 (overlaps B prefetch) ---
            if (doConv) {
                #pragma unroll
                for (int it = 0; it < 8; ++it) {
                    int idx = tid + (it << 8);
                    int row = idx >> 5;
                    int c4  = idx & 31;
                    int grow = rowBase + row;
                    float4 v = make_float4(0.f, 0.f, 0.f, 0.f);
                    if (grow < n) {
                        v = *(const float4*)&Ap[grow * 128 + c4 * 4];
                        if (rsp) {
                            float s = __ldg(&rsp[grow]);
                            v.x *= s; v.y *= s; v.z *= s; v.w *= s;
                        }
                    }
                    __nv_bfloat16 hx = __float2bfloat16(v.x);
                    __nv_bfloat16 hy = __float2bfloat16(v.y);
                    __nv_bfloat16 hz = __float2bfloat16(v.z);
                    __nv_bfloat16 hw = __float2bfloat16(v.w);
                    __nv_bfloat162 h01; h01.x = hx; h01.y = hy;
                    __nv_bfloat162 h23; h23.x = hz; h23.y = hw;
                    __nv_bfloat162 l01, l23;
                    l01.x = __float2bfloat16(v.x - __bfloat162float(hx));
                    l01.y = __float2bfloat16(v.y - __bfloat162float(hy));
                    l23.x = __float2bfloat16(v.z - __bfloat162float(hz));
                    l23.y = __float2bfloat16(v.w - __bfloat162float(hw));
                    int o = row * WPAD + c4 * 4;
                    *(__nv_bfloat162*)&sm[o]            = h01;
                    *(__nv_bfloat162*)&sm[o + 2]        = h23;
                    *(__nv_bfloat162*)&sm[8704 + o]     = l01;
                    *(__nv_bfloat162*)&sm[8704 + o + 2] = l23;
                }
            }
            asm volatile("cp.async.wait_group 0;" ::: "memory");
            __syncthreads();

            // --- mainloop: 3 split terms x 8 k-steps ---
            #pragma unroll
            for (int sel = 0; sel < 3; ++sel) {
                const uint32_t aB = (sel == 1) ? aLoAddr : aHiAddr;
                const uint32_t bB = (sel == 2) ? bLoAddr : bHiAddr;
                #pragma unroll
                for (int kk = 0; kk < 8; ++kk) {
                    uint32_t ko = kk * 32;
                    uint32_t a0[4], a1[4], b0[4], b1[4];
                    ldsm4(a0, aB + aoff0 + ko);
                    ldsm4(a1, aB + aoff1 + ko);
                    ldsm4(b0, bB + boff0 + ko);
                    ldsm4(b1, bB + boff1 + ko);
                    mma_bf16(acc[0][0], a0, &b0[0]);
                    mma_bf16(acc[0][1], a0, &b0[2]);
                    mma_bf16(acc[0][2], a0, &b1[0]);
                    mma_bf16(acc[0][3], a0, &b1[2]);
                    mma_bf16(acc[1][0], a1, &b0[0]);
                    mma_bf16(acc[1][1], a1, &b0[2]);
                    mma_bf16(acc[1][2], a1, &b1[0]);
                    mma_bf16(acc[1][3], a1, &b1[2]);
                }
            }
        }

        if (J.chainOut) {
            // --- epilogue -> smem A (bf16 hi/lo) for the next chained job ---
            __syncthreads();   // all warps done reading A smem
            #pragma unroll
            for (int mt = 0; mt < 2; ++mt) {
                #pragma unroll
                for (int half = 0; half < 2; ++half) {
                    int rloc = warpM * 32 + mt * 16 + tq + half * 8;
                    #pragma unroll
                    for (int nt = 0; nt < 4; ++nt) {
                        int col = warpN * 32 + nt * 8 + tr * 2;
                        float v0 = acc[mt][nt][half * 2];
                        float v1 = acc[mt][nt][half * 2 + 1];
                        if (J.bias) {
                            v0 += __ldg(&J.bias[col]);
                            v1 += __ldg(&J.bias[col + 1]);
                        }
                        if (J.actMode == 1)      { v0 = mishf(v0); v1 = mishf(v1); }
                        else if (J.actMode == 2) { v0 = mishf(mishf(v0)); v1 = mishf(mishf(v1)); }
                        __nv_bfloat16 h0 = __float2bfloat16(v0);
                        __nv_bfloat16 h1 = __float2bfloat16(v1);
                        __nv_bfloat162 hh; hh.x = h0; hh.y = h1;
                        __nv_bfloat162 ll;
                        ll.x = __float2bfloat16(v0 - __bfloat162float(h0));
                        ll.y = __float2bfloat16(v1 - __bfloat162float(h1));
                        int o = rloc * WPAD + col;
                        *(__nv_bfloat162*)&sm[o]        = hh;
                        *(__nv_bfloat162*)&sm[8704 + o] = ll;
                    }
                }
            }
        } else {
            // --- epilogue -> global ---
            #pragma unroll
            for (int mt = 0; mt < 2; ++mt) {
                #pragma unroll
                for (int half = 0; half < 2; ++half) {
                    int grow = rowBase + warpM * 32 + mt * 16 + tq + half * 8;
                    if (grow >= n) continue;
                    float brs = J.biasRowScale ? __ldg(&J.biasRowScale[grow]) : 1.0f;
                    #pragma unroll
                    for (int nt = 0; nt < 4; ++nt) {
                        int col = warpN * 32 + nt * 8 + tr * 2;
                        float v0 = acc[mt][nt][half * 2];
                        float v1 = acc[mt][nt][half * 2 + 1];
                        if (J.bias) {
                            v0 += __ldg(&J.bias[col])     * brs;
                            v1 += __ldg(&J.bias[col + 1]) * brs;
                        }
                        if (J.Cadd) {
                            float2 ca = *(const float2*)&J.Cadd[grow * 128 + col];
                            v0 += ca.x; v1 += ca.y;
                        }
                        if (J.actMode == 1)      { v0 = mishf(v0); v1 = mishf(v1); }
                        else if (J.actMode == 2) { v0 = mishf(mishf(v0)); v1 = mishf(mishf(v1)); }
                        *(float2*)&J.C[grow * 128 + col] = make_float2(v0, v1);
                    }
                }
            }
        }
    }
}

// ---------------------------------------------------------------------------
// Edge phase: 3 L2-resident passes, one warp per edge.
// ---------------------------------------------------------------------------
__global__ void __launch_bounds__(256) edge_node(
    const int* __restrict__ ei,
    const float4* __restrict__ Un, const float4* __restrict__ Vn,
    float4* Pn, int E)
{
    int e = blockIdx.x * 8 + (threadIdx.x >> 5);
    if (e >= E) return;
    int lane = threadIdx.x & 31;
    int src = ei[e];
    int dst = ei[E + e];
    int di = dst * 32 + lane;
    float4 u = Un[di], v = Vn[src * 32 + lane], m;
    m.x = mishf(u.x + v.x); m.y = mishf(u.y + v.y);
    m.z = mishf(u.z + v.z); m.w = mishf(u.w + v.w);
    red_add_v4(&Pn[di], m);
}

__global__ void __launch_bounds__(256) edge_edge(
    const int* __restrict__ ei, const int* __restrict__ bt,
    const float* __restrict__ conv_w, const float* __restrict__ conv_b,
    const float* __restrict__ b_el,
    const float4* __restrict__ Ue, const float4* __restrict__ Ve,
    float4* Pe, int E)
{
    int e = blockIdx.x * 8 + (threadIdx.x >> 5);
    if (e >= E) return;
    int lane = threadIdx.x & 31;
    int src = ei[e];
    int dst = ei[E + e];
    float norm = conv_w[bt[e]] + conv_b[0];
    int di = dst * 32 + lane;
    float4 u = Ue[di], v = Ve[src * 32 + lane];
    float4 b = ((const float4*)b_el)[lane];
    float4 m;
    m.x = mishf(norm * (u.x + v.x) + b.x);
    m.y = mishf(norm * (u.y + v.y) + b.y);
    m.z = mishf(norm * (u.z + v.z) + b.z);
    m.w = mishf(norm * (u.w + v.w) + b.w);
    red_add_v4(&Pe[di], m);
}

__global__ void __launch_bounds__(256) edge_struct(
    const int* __restrict__ ei, const float* __restrict__ coords,
    const float4* __restrict__ x,
    float4* T, float* s_arr, float* deg_arr, int E)
{
    int e = blockIdx.x * 8 + (threadIdx.x >> 5);
    if (e >= E) return;
    int lane = threadIdx.x & 31;
    int src = ei[e];
    int dst = ei[E + e];
    float dx = coords[src * 3 + 0] - coords[dst * 3 + 0];
    float dy = coords[src * 3 + 1] - coords[dst * 3 + 1];
    float dz = coords[src * 3 + 2] - coords[dst * 3 + 2];
    float d2 = dx * dx + dy * dy + dz * dz;
    float4 xs = x[src * 32 + lane];
    float4 m = make_float4(d2 * xs.x, d2 * xs.y, d2 * xs.z, d2 * xs.w);
    red_add_v4(&T[dst * 32 + lane], m);
    if (lane == 0) {
        atomicAdd(&s_arr[dst], d2);
        atomicAdd(&deg_arr[dst], 1.0f);
    }
}

// ---------------------------------------------------------------------------
__global__ void attention_kernel(
    const float4* __restrict__ e0, const float4* __restrict__ e1,
    const float4* __restrict__ e2,
    const float4* __restrict__ f0, const float4* __restrict__ f1,
    const float4* __restrict__ f2,
    float4* __restrict__ att, int n4)
{
    int i = blockIdx.x * blockDim.x + threadIdx.x;
    if (i >= n4) return;
    float4 a0 = e0[i], a1 = e1[i], a2 = e2[i];
    float4 g0 = f0[i], g1 = f1[i], g2 = f2[i];
    float4 o;
    {
        float m = fmaxf(a0.x, fmaxf(a1.x, a2.x));
        float p0 = __expf(a0.x - m), p1 = __expf(a1.x - m), p2 = __expf(a2.x - m);
        o.x = __fdividef(p0 * g0.x + p1 * g1.x + p2 * g2.x, p0 + p1 + p2);
    }
    {
        float m = fmaxf(a0.y, fmaxf(a1.y, a2.y));
        float p0 = __expf(a0.y - m), p1 = __expf(a1.y - m), p2 = __expf(a2.y - m);
        o.y = __fdividef(p0 * g0.y + p1 * g1.y + p2 * g2.y, p0 + p1 + p2);
    }
    {
        float m = fmaxf(a0.z, fmaxf(a1.z, a2.z));
        float p0 = __expf(a0.z - m), p1 = __expf(a1.z - m), p2 = __expf(a2.z - m);
        o.z = __fdividef(p0 * g0.z + p1 * g1.z + p2 * g2.z, p0 + p1 + p2);
    }
    {
        float m = fmaxf(a0.w, fmaxf(a1.w, a2.w));
        float p0 = __expf(a0.w - m), p1 = __expf(a1.w - m), p2 = __expf(a2.w - m);
        o.w = __fdividef(p0 * g0.w + p1 * g1.w + p2 * g2.w, p0 + p1 + p2);
    }
    att[i] = o;
}

__global__ void bnstat_kernel(const float* __restrict__ H,
                              float* sum, float* sq, int n)
{
    int d  = threadIdx.x;
    int r0 = blockIdx.x * 256;
    int r1 = min(r0 + 256, n);
    float s = 0.f, q = 0.f;
    for (int r = r0; r < r1; ++r) {
        float v = H[r * 128 + d];
        s += v; q += v * v;
    }
    atomicAdd(&sum[d], s);
    atomicAdd(&sq[d],  q);
}

__global__ void final_kernel(const float* __restrict__ H,
                             const float* __restrict__ sum,
                             const float* __restrict__ sq,
                             const float* __restrict__ gamma,
                             const float* __restrict__ beta,
                             float* __restrict__ out, int n)
{
    int i = blockIdx.x * blockDim.x + threadIdx.x;
    if (i >= n * 128) return;
    int d = i & 127;
    float invn = 1.0f / (float)n;
    float mean = sum[d] * invn;
    float var  = sq[d] * invn - mean * mean;
    float v = (H[i] - mean) * rsqrtf(var + 1e-5f) * gamma[d] + beta[d];
    out[i] = mishf(v);
}

// ---------------------------------------------------------------------------
// Host launch
// ---------------------------------------------------------------------------
static float* symaddr(const void* sym) {
    void* p = nullptr;
    cudaGetSymbolAddress(&p, sym);
    return (float*)p;
}

#define GEMM_SMEM 104448

static Job mkjob(const float* A, int w1, float* C, int act,
                 const float* bias = nullptr, int convertA = 1,
                 const float* A2 = nullptr, int w2 = -1,
                 const float* rowScale = nullptr,
                 const float* brs = nullptr, const float* Cadd = nullptr,
                 int chainOut = 0)
{
    Job j;
    j.A = A; j.A2 = A2; j.rowScale = rowScale; j.bias = bias;
    j.biasRowScale = brs; j.Cadd = Cadd; j.C = C;
    j.w1 = w1; j.w2 = w2; j.actMode = act; j.convertA = convertA;
    j.chainOut = chainOut;
    return j;
}

extern "C" void kernel_launch(void* const* d_in, const int* in_sizes, int n_in,
                              void* d_out, int out_size)
{
    const float* x       = (const float*)d_in[0];
    const float* coords  = (const float*)d_in[1];
    const int*   ei      = (const int*)  d_in[2];
    const int*   bt      = (const int*)  d_in[3];
    const float* W_nb    = (const float*)d_in[4];
    const float* b_nb    = (const float*)d_in[5];
    const float* W_nout  = (const float*)d_in[6];
    const float* b_nout  = (const float*)d_in[7];
    const float* conv_w  = (const float*)d_in[8];
    const float* conv_b  = (const float*)d_in[9];
    const float* W_el    = (const float*)d_in[10];
    const float* b_el    = (const float*)d_in[11];
    const float* W_eout  = (const float*)d_in[12];
    const float* b_eout  = (const float*)d_in[13];
    const float* W_coord = (const float*)d_in[14];
    const float* b_coord = (const float*)d_in[15];
    const float* W_pair  = (const float*)d_in[16];
    const float* b_pair  = (const float*)d_in[17];
    const float* W_sout  = (const float*)d_in[18];
    const float* b_sout  = (const float*)d_in[19];
    const float* W_init  = (const float*)d_in[20];
    const float* feat_lin= (const float*)d_in[21];
    const float* W_att   = (const float*)d_in[22];
    const float* W_agg   = (const float*)d_in[23];
    const float* gamma   = (const float*)d_in[24];
    const float* beta    = (const float*)d_in[25];

    const int N = in_sizes[0] / 128;
    const int E = in_sizes[2] / 2;

    static bool attrSet = false;
    if (!attrSet) {
        cudaFuncSetAttribute(mma_gemm,
            cudaFuncAttributeMaxDynamicSharedMemorySize, GEMM_SMEM);
        attrSet = true;
    }

    float* Un    = symaddr(g_b0);
    float* Vn    = symaddr(g_b1);
    float* Ue    = symaddr(g_b2);
    float* Ve    = symaddr(g_b3);
    float* Hagg  = symaddr(g_b4);
    float* Einit = symaddr(g_b5);
    float* Pn    = symaddr(g_b6);
    float* Pe    = symaddr(g_b7);
    float* T     = symaddr(g_b8);
    float* Fn    = symaddr(g_b9);
    float* Fe    = symaddr(g_b10);
    float* Qp    = symaddr(g_b11);
    float* Fs    = symaddr(g_b13);
    float* sArr  = symaddr(g_s);
    float* dArr  = symaddr(g_deg);
    float* bnS   = symaddr(g_bnsum);
    float* bnQ   = symaddr(g_bnsq);
    float* E0 = Un; float* E1 = Vn; float* E2 = Ue;
    float* Att = Ve;

    const size_t vecBytes = (size_t)N * 128 * sizeof(float);
    cudaMemsetAsync(Pn,  0, vecBytes);
    cudaMemsetAsync(Pe,  0, vecBytes);
    cudaMemsetAsync(T,   0, vecBytes);
    cudaMemsetAsync(sArr, 0, N * sizeof(float));
    cudaMemsetAsync(dArr, 0, N * sizeof(float));
    cudaMemsetAsync(bnS, 0, 128 * sizeof(float));
    cudaMemsetAsync(bnQ, 0, 128 * sizeof(float));

    // Weight indices in g_wt:
    //  0 Wnb_top  1 Wnb_bot  2 Wel_top  3 Wel_bot  4 W_init  5 Watt_top
    //  6 W_nout   7 W_eout   8 Wc_top   9 Wc_bot  10 W_pair 11 Ws_top
    // 12 Ws_bot  13 fl0     14 fl1     15 fl2     16 Watt_bot 17 W_agg
    WPtrs wp;
    wp.p[0]  = W_nb;               wp.p[1]  = W_nb + 128 * 128;
    wp.p[2]  = W_el;               wp.p[3]  = W_el + 128 * 128;
    wp.p[4]  = W_init;             wp.p[5]  = W_att;
    wp.p[6]  = W_nout;             wp.p[7]  = W_eout;
    wp.p[8]  = W_coord;            wp.p[9]  = W_coord + 128 * 128;
    wp.p[10] = W_pair;             wp.p[11] = W_sout;
    wp.p[12] = W_sout + 128 * 128; wp.p[13] = feat_lin;
    wp.p[14] = feat_lin + 128 * 128; wp.p[15] = feat_lin + 2 * 128 * 128;
    wp.p[16] = W_att + 128 * 128;  wp.p[17] = W_agg;

    setup_weights<<<dim3(18, 8), 256>>>(wp);

    dim3 gb(256);
    dim3 gg((N + 63) / 64);

    JobList jl;

    // --- L1: 4 projections + (Hini chain -> Einit), all sharing A=x ---
    jl.count = 6;
    jl.j[0] = mkjob(x, 0, Un,   0, b_nb, 1);
    jl.j[1] = mkjob(x, 1, Vn,   0, nullptr, 0);
    jl.j[2] = mkjob(x, 2, Ue,   0, nullptr, 0);
    jl.j[3] = mkjob(x, 3, Ve,   0, nullptr, 0);
    jl.j[4] = mkjob(x, 4, nullptr, 2, nullptr, 0, nullptr, -1, nullptr, nullptr, nullptr, 1);
    jl.j[5] = mkjob(x, 5, Einit, 0, nullptr, 0);   // consumes chained Hini
    mma_gemm<<<gg, gb, GEMM_SMEM>>>(jl, N);

    // --- edge phase: 3 L2-resident passes ---
    int egrid = (E + 7) / 8;
    edge_node<<<egrid, 256>>>(ei, (const float4*)Un, (const float4*)Vn,
                              (float4*)Pn, E);
    edge_edge<<<egrid, 256>>>(ei, bt, conv_w, conv_b, b_el,
                              (const float4*)Ue, (const float4*)Ve,
                              (float4*)Pe, E);
    edge_struct<<<egrid, 256>>>(ei, coords, (const float4*)x,
                                (float4*)T, sArr, dArr, E);

    // --- L3: Fn, Fe, Qp ---
    jl.count = 3;
    jl.j[0] = mkjob(Pn, 6, Fn, 1, b_nout, 1);
    jl.j[1] = mkjob(Pe, 7, Fe, 1, b_eout, 1);
    jl.j[2] = mkjob(x, 8, Qp, 0, b_coord, 1, T, 9, sArr, dArr);
    mma_gemm<<<gg, gb, GEMM_SMEM>>>(jl, N);

    // --- L4: Q chain -> Fs = mish(Q@Ws_bot + x@Ws_top + b_sout) ---
    jl.count = 2;
    jl.j[0] = mkjob(Qp, 10, nullptr, 1, b_pair, 1, nullptr, -1, nullptr, nullptr, nullptr, 1);
    jl.j[1] = mkjob(x, 12, Fs, 1, b_sout, 0, x, 11);
    mma_gemm<<<gg, gb, GEMM_SMEM>>>(jl, N);

    // --- L5: per path, HR chain (mish^2) -> E_f = HR@Watt_bot + Einit ---
    jl.count = 6;
    jl.j[0] = mkjob(Fn, 13, nullptr, 2, nullptr, 1, nullptr, -1, nullptr, nullptr, nullptr, 1);
    jl.j[1] = mkjob(x, 16, E0, 0, nullptr, 0, nullptr, -1, nullptr, nullptr, Einit);
    jl.j[2] = mkjob(Fe, 14, nullptr, 2, nullptr, 1, nullptr, -1, nullptr, nullptr, nullptr, 1);
    jl.j[3] = mkjob(x, 16, E1, 0, nullptr, 0, nullptr, -1, nullptr, nullptr, Einit);
    jl.j[4] = mkjob(Fs, 15, nullptr, 2, nullptr, 1, nullptr, -1, nullptr, nullptr, nullptr, 1);
    jl.j[5] = mkjob(x, 16, E2, 0, nullptr, 0, nullptr, -1, nullptr, nullptr, Einit);
    mma_gemm<<<gg, gb, GEMM_SMEM>>>(jl, N);

    int n4 = N * 32;
    attention_kernel<<<(n4 + 255) / 256, 256>>>(
        (const float4*)E0, (const float4*)E1, (const float4*)E2,
        (const float4*)Fn, (const float4*)Fe, (const float4*)Fs,
        (float4*)Att, n4);

    // --- L6: Hagg = Att @ W_agg ---
    jl.count = 1;
    jl.j[0] = mkjob(Att, 17, Hagg, 0);
    mma_gemm<<<gg, gb, GEMM_SMEM>>>(jl, N);

    bnstat_kernel<<<(N + 255) / 256, 128>>>(Hagg, bnS, bnQ, N);
    final_kernel<<<(N * 128 + 255) / 256, 256>>>(Hagg, bnS, bnQ, gamma, beta,
                                                 (float*)d_out, N);
}